// round 1
// baseline (speedup 1.0000x reference)
#include <cuda_runtime.h>
#include <cuda_bf16.h>

typedef unsigned long long ull;

#define BN_TOTAL (256 * 16384)
#define N_SEQ    16384

// Scratch for dg = mlp(t) (+1).  __device__ global: allowed scratch.
__device__ float g_dg[BN_TOTAL];

// ---------------------------------------------------------------------------
// packed f32x2 helpers (Blackwell FFMA2 — only reachable via PTX fma.rn.f32x2)
// ---------------------------------------------------------------------------
__device__ __forceinline__ ull pack2(float a, float b) {
    ull r; asm("mov.b64 %0, {%1, %2};" : "=l"(r) : "f"(a), "f"(b)); return r;
}
__device__ __forceinline__ void unpack2(ull v, float& a, float& b) {
    asm("mov.b64 {%0, %1}, %2;" : "=f"(a), "=f"(b) : "l"(v));
}
__device__ __forceinline__ ull bcast2(float a) {
    ull r; asm("mov.b64 %0, {%1, %1};" : "=l"(r) : "f"(a)); return r;
}
__device__ __forceinline__ void ffma2(ull& d, ull a, ull b) {
    asm("fma.rn.f32x2 %0, %1, %2, %0;" : "+l"(d) : "l"(a), "l"(b));
}

// numerically stable softplus: max(x,0) + log(1 + exp(-|x|))
__device__ __forceinline__ float splus(float x) {
    float e = __expf(-fabsf(x));
    return fmaxf(x, 0.0f) + __logf(1.0f + e);
}

// ---------------------------------------------------------------------------
// dense layer: hout = softplus(W * hin + b); W stored transposed in smem as
// sWt[k*OUT + j] so each input scalar k broadcasts against contiguous j-pairs.
// All loops fully unrolled: register-resident ull (f32x2) arrays.
// ---------------------------------------------------------------------------
template <int IN, int OUT>
__device__ __forceinline__ void dense_sp(const ull* __restrict__ hin,
                                         ull* __restrict__ hout,
                                         const float* __restrict__ sWt,
                                         const float* __restrict__ sB) {
    constexpr int IN2 = IN / 2, OUT2 = OUT / 2;
    const float2* b2 = reinterpret_cast<const float2*>(sB);
#pragma unroll
    for (int j = 0; j < OUT2; j++) {
        float2 bb = b2[j];
        hout[j] = pack2(bb.x, bb.y);
    }
#pragma unroll
    for (int k2 = 0; k2 < IN2; k2++) {
        float x0, x1;
        unpack2(hin[k2], x0, x1);
        ull xx0 = bcast2(x0), xx1 = bcast2(x1);
        const ull* w0 = reinterpret_cast<const ull*>(sWt + (2 * k2) * OUT);
        const ull* w1 = reinterpret_cast<const ull*>(sWt + (2 * k2 + 1) * OUT);
#pragma unroll
        for (int j = 0; j < OUT2; j++) ffma2(hout[j], w0[j], xx0);
#pragma unroll
        for (int j = 0; j < OUT2; j++) ffma2(hout[j], w1[j], xx1);
    }
#pragma unroll
    for (int j = 0; j < OUT2; j++) {
        float a, b;
        unpack2(hout[j], a, b);
        hout[j] = pack2(splus(a), splus(b));
    }
}

// ---------------------------------------------------------------------------
// Kernel A: dg[i] = mlp(t[i]) + 1   (one thread per point)
// ---------------------------------------------------------------------------
__global__ __launch_bounds__(256) void mlp_kernel(
    const float* __restrict__ t,
    const float* __restrict__ W1, const float* __restrict__ b1,
    const float* __restrict__ W2, const float* __restrict__ b2,
    const float* __restrict__ W3, const float* __restrict__ b3,
    const float* __restrict__ W4, const float* __restrict__ b4,
    const float* __restrict__ W5, const float* __restrict__ b5,
    int total)
{
    __shared__ __align__(16) float sW1[32], sB1[32];
    __shared__ __align__(16) float sWt2[32 * 64], sB2[64];
    __shared__ __align__(16) float sWt3[64 * 64], sB3[64];
    __shared__ __align__(16) float sWt4[64 * 32], sB4[32];
    __shared__ __align__(16) float sW5[32];
    __shared__ float sB5;

    int tid = threadIdx.x;
    // cooperative transposed weight load
    for (int i = tid; i < 64 * 32; i += 256) {   // W2: [64,32] -> sWt2[k*64+j]
        int j = i / 32, k = i % 32;
        sWt2[k * 64 + j] = W2[i];
    }
    for (int i = tid; i < 64 * 64; i += 256) {   // W3: [64,64] -> sWt3[k*64+j]
        int j = i / 64, k = i % 64;
        sWt3[k * 64 + j] = W3[i];
    }
    for (int i = tid; i < 32 * 64; i += 256) {   // W4: [32,64] -> sWt4[k*32+j]
        int j = i / 64, k = i % 64;
        sWt4[k * 32 + j] = W4[i];
    }
    if (tid < 32) {
        sW1[tid] = W1[tid]; sB1[tid] = b1[tid];
        sB4[tid] = b4[tid]; sW5[tid] = W5[tid];
    }
    if (tid < 64) { sB2[tid] = b2[tid]; sB3[tid] = b3[tid]; }
    if (tid == 0) sB5 = b5[0];
    __syncthreads();

    int gid = blockIdx.x * 256 + tid;
    if (gid >= total) return;

    float tv = t[gid];

    ull A[32], Bv[32];

    // layer 1: 1 -> 32
#pragma unroll
    for (int j = 0; j < 16; j++) {
        float h0 = splus(fmaf(tv, sW1[2 * j],     sB1[2 * j]));
        float h1 = splus(fmaf(tv, sW1[2 * j + 1], sB1[2 * j + 1]));
        A[j] = pack2(h0, h1);
    }

    dense_sp<32, 64>(A,  Bv, sWt2, sB2);   // layer 2
    dense_sp<64, 64>(Bv, A,  sWt3, sB3);   // layer 3
    dense_sp<64, 32>(A,  Bv, sWt4, sB4);   // layer 4

    // layer 5: 32 -> 1, then +1
    float acc = sB5;
#pragma unroll
    for (int k2 = 0; k2 < 16; k2++) {
        float x0, x1;
        unpack2(Bv[k2], x0, x1);
        acc = fmaf(sW5[2 * k2],     x0, acc);
        acc = fmaf(sW5[2 * k2 + 1], x1, acc);
    }
    g_dg[gid] = splus(acc) + 1.0f;
}

// ---------------------------------------------------------------------------
// Kernel B: per-row cumulative trapezoid. One block (512 threads) per row,
// each thread scans SEG=32 contiguous elements, hierarchical block scan.
// ---------------------------------------------------------------------------
__global__ __launch_bounds__(512) void scan_kernel(
    const float* __restrict__ t, float* __restrict__ out)
{
    const int SEG = N_SEQ / 512;  // 32
    int row = blockIdx.x;
    int tid = threadIdx.x;
    const float* tr = t + (size_t)row * N_SEQ;
    const float* dr = g_dg + (size_t)row * N_SEQ;
    float* orow = out + (size_t)row * N_SEQ;

    int s = tid * SEG;
    float tp, dp;
    if (s == 0) { tp = tr[0]; dp = dr[0]; }
    else        { tp = tr[s - 1]; dp = dr[s - 1]; }

    float e[SEG];
    float run = 0.0f;
#pragma unroll
    for (int i = 0; i < SEG; i++) {
        int idx = s + i;
        float tc = tr[idx], dc = dr[idx];
        float ei = (idx == 0) ? 0.0f : 0.5f * (dc + dp) * (tc - tp);
        run += ei;
        e[i] = run;
        tp = tc; dp = dc;
    }

    // warp inclusive scan of per-thread totals
    float v = run;
    unsigned mask = 0xffffffffu;
    int lane = tid & 31, warp = tid >> 5;
#pragma unroll
    for (int off = 1; off < 32; off <<= 1) {
        float n = __shfl_up_sync(mask, v, off);
        if (lane >= off) v += n;
    }

    __shared__ float wsum[16];
    if (lane == 31) wsum[warp] = v;
    __syncthreads();
    if (warp == 0) {
        float w = (lane < 16) ? wsum[lane] : 0.0f;
#pragma unroll
        for (int off = 1; off < 16; off <<= 1) {
            float n = __shfl_up_sync(mask, w, off);
            if (lane >= off) w += n;
        }
        if (lane < 16) wsum[lane] = w;  // inclusive warp-total scan
    }
    __syncthreads();

    float base = ((warp > 0) ? wsum[warp - 1] : 0.0f) + (v - run);
#pragma unroll
    for (int i = 0; i < SEG; i++) orow[s + i] = base + e[i];
}

// ---------------------------------------------------------------------------
extern "C" void kernel_launch(void* const* d_in, const int* in_sizes, int n_in,
                              void* d_out, int out_size) {
    const float* t  = (const float*)d_in[0];
    const float* W1 = (const float*)d_in[1];
    const float* b1 = (const float*)d_in[2];
    const float* W2 = (const float*)d_in[3];
    const float* b2 = (const float*)d_in[4];
    const float* W3 = (const float*)d_in[5];
    const float* b3 = (const float*)d_in[6];
    const float* W4 = (const float*)d_in[7];
    const float* b4 = (const float*)d_in[8];
    const float* W5 = (const float*)d_in[9];
    const float* b5 = (const float*)d_in[10];
    float* out = (float*)d_out;

    int total = in_sizes[0];           // B * N (= 4194304)
    int nrows = total / N_SEQ;         // B (= 256)

    int blocks = (total + 255) / 256;
    mlp_kernel<<<blocks, 256>>>(t, W1, b1, W2, b2, W3, b3, W4, b4, W5, b5, total);
    scan_kernel<<<nrows, 512>>>(t, out);
}

// round 2
// speedup vs baseline: 1.2070x; 1.2070x over previous
#include <cuda_runtime.h>
#include <cuda_bf16.h>

typedef unsigned long long ull;

#define N_SEQ    16384
#define BN_TOTAL (256 * 16384)
#define M_BLK    128      // points per block
#define THREADS  128

// scratch: dg values + transposed weights
__device__ float g_dg[BN_TOTAL];
__device__ float g_wt[8192];   // [0:2048) W2t, [2048:6144) W3t, [6144:8192) W4t

// ---------------------------------------------------------------------------
// packed f32x2 helpers (Blackwell FFMA2 via PTX fma.rn.f32x2)
// ---------------------------------------------------------------------------
__device__ __forceinline__ void unpack2(ull v, float& a, float& b) {
    asm("mov.b64 {%0, %1}, %2;" : "=f"(a), "=f"(b) : "l"(v));
}
__device__ __forceinline__ ull bcast2(float a) {
    ull r; asm("mov.b64 %0, {%1, %1};" : "=l"(r) : "f"(a)); return r;
}
__device__ __forceinline__ void ffma2(ull& d, ull a, ull b) {
    asm("fma.rn.f32x2 %0, %1, %2, %0;" : "+l"(d) : "l"(a), "l"(b));
}

// stable softplus with fast MUFU paths
__device__ __forceinline__ float splus(float x) {
    float e = __expf(-fabsf(x));
    return fmaxf(x, 0.0f) + __logf(1.0f + e);
}

// ---------------------------------------------------------------------------
// pre-kernel: transpose W2/W3/W4 into g_wt, once
// ---------------------------------------------------------------------------
__global__ void transpose_w_kernel(const float* __restrict__ W2,
                                   const float* __restrict__ W3,
                                   const float* __restrict__ W4) {
    int tid = threadIdx.x;
    for (int d = tid; d < 2048; d += 256) {         // W2 [64,32] -> W2t[k*64+j]
        int k = d >> 6, j = d & 63;
        g_wt[d] = W2[j * 32 + k];
    }
    for (int d = tid; d < 4096; d += 256) {         // W3 [64,64] -> W3t[k*64+j]
        int k = d >> 6, j = d & 63;
        g_wt[2048 + d] = W3[j * 64 + k];
    }
    for (int d = tid; d < 2048; d += 256) {         // W4 [32,64] -> W4t[k*32+j]
        int k = d >> 5, j = d & 31;
        g_wt[6144 + d] = W4[j * 64 + k];
    }
}

// ---------------------------------------------------------------------------
// register-tiled dense layer: out = softplus(Wt^T * in + b)
//   sIn  : [K][128]    activations (channel-major, point-contiguous)
//   sOut : [NOUT][128]
//   sWt  : [K][NOUT]
// thread (r, jg): points m0 = r*8 (4 f32x2 pairs), channels j0 = jg*TN
// ---------------------------------------------------------------------------
template <int K, int TN>
__device__ __forceinline__ void layer(const float* __restrict__ sIn,
                                      float* __restrict__ sOut,
                                      const float* __restrict__ sWt,
                                      const float* __restrict__ sBias,
                                      int m0, int j0) {
    constexpr int NOUT_STRIDE = (TN == 8) ? 64 : 32;
    ull c[TN][4];
#pragma unroll
    for (int j = 0; j < TN; j++) {
        ull bb = bcast2(sBias[j0 + j]);
#pragma unroll
        for (int p = 0; p < 4; p++) c[j][p] = bb;
    }
#pragma unroll 4
    for (int k = 0; k < K; k++) {
        const ull* xr = reinterpret_cast<const ull*>(sIn + k * M_BLK + m0);
        ull x0 = xr[0], x1 = xr[1], x2 = xr[2], x3 = xr[3];
        const float* wr = sWt + k * NOUT_STRIDE + j0;
        float4 wa = *reinterpret_cast<const float4*>(wr);
        ull wd0 = bcast2(wa.x), wd1 = bcast2(wa.y),
            wd2 = bcast2(wa.z), wd3 = bcast2(wa.w);
        ffma2(c[0][0], x0, wd0); ffma2(c[0][1], x1, wd0);
        ffma2(c[0][2], x2, wd0); ffma2(c[0][3], x3, wd0);
        ffma2(c[1][0], x0, wd1); ffma2(c[1][1], x1, wd1);
        ffma2(c[1][2], x2, wd1); ffma2(c[1][3], x3, wd1);
        ffma2(c[2][0], x0, wd2); ffma2(c[2][1], x1, wd2);
        ffma2(c[2][2], x2, wd2); ffma2(c[2][3], x3, wd2);
        ffma2(c[3][0], x0, wd3); ffma2(c[3][1], x1, wd3);
        ffma2(c[3][2], x2, wd3); ffma2(c[3][3], x3, wd3);
        if (TN == 8) {
            float4 wb = *reinterpret_cast<const float4*>(wr + 4);
            ull wd4 = bcast2(wb.x), wd5 = bcast2(wb.y),
                wd6 = bcast2(wb.z), wd7 = bcast2(wb.w);
            ffma2(c[4][0], x0, wd4); ffma2(c[4][1], x1, wd4);
            ffma2(c[4][2], x2, wd4); ffma2(c[4][3], x3, wd4);
            ffma2(c[5][0], x0, wd5); ffma2(c[5][1], x1, wd5);
            ffma2(c[5][2], x2, wd5); ffma2(c[5][3], x3, wd5);
            ffma2(c[6][0], x0, wd6); ffma2(c[6][1], x1, wd6);
            ffma2(c[6][2], x2, wd6); ffma2(c[6][3], x3, wd6);
            ffma2(c[7][0], x0, wd7); ffma2(c[7][1], x1, wd7);
            ffma2(c[7][2], x2, wd7); ffma2(c[7][3], x3, wd7);
        }
    }
    // softplus epilogue + store
#pragma unroll
    for (int j = 0; j < TN; j++) {
        float* orow = sOut + (j0 + j) * M_BLK + m0;
#pragma unroll
        for (int p = 0; p < 4; p++) {
            float a, b;
            unpack2(c[j][p], a, b);
            *reinterpret_cast<float2*>(orow + 2 * p) =
                make_float2(splus(a), splus(b));
        }
    }
}

// ---------------------------------------------------------------------------
// MLP kernel: one block = 128 points through all 5 layers via SMEM staging
// ---------------------------------------------------------------------------
// dynamic smem layout (float offsets):
#define SM_A    0            // [64][128]
#define SM_B    8192         // [64][128]
#define SM_W2T  16384        // [32][64]
#define SM_W3T  18432        // [64][64]
#define SM_W4T  22528        // [64][32]
#define SM_B2   24576        // 64
#define SM_B3   24640        // 64
#define SM_B4   24704        // 32
#define SM_W1   24736        // 32
#define SM_B1   24768        // 32
#define SM_W5   24800        // 32
#define SM_B5   24832        // 1
#define SMEM_FLOATS 24836
#define SMEM_BYTES  (SMEM_FLOATS * 4)

__global__ __launch_bounds__(THREADS) void mlp_tiled_kernel(
    const float* __restrict__ t,
    const float* __restrict__ b1g, const float* __restrict__ b2g,
    const float* __restrict__ b3g, const float* __restrict__ b4g,
    const float* __restrict__ W1g, const float* __restrict__ W5g,
    const float* __restrict__ b5g)
{
    extern __shared__ __align__(16) float sm[];
    int tid = threadIdx.x;
    int gbase = blockIdx.x * M_BLK;

    // stage transposed weights (coalesced from scratch) + small params
    for (int i = tid; i < 8192; i += THREADS) sm[SM_W2T + i] = g_wt[i];
    if (tid < 64) { sm[SM_B2 + tid] = b2g[tid]; sm[SM_B3 + tid] = b3g[tid]; }
    if (tid < 32) {
        sm[SM_B4 + tid] = b4g[tid];
        sm[SM_W1 + tid] = W1g[tid];
        sm[SM_B1 + tid] = b1g[tid];
        sm[SM_W5 + tid] = W5g[tid];
    }
    if (tid == 0) sm[SM_B5] = b5g[0];

    // layer 1: 1 -> 32, thread handles its own point, column write
    float tv = t[gbase + tid];
    __syncthreads();
#pragma unroll
    for (int j = 0; j < 32; j++) {
        sm[SM_A + j * M_BLK + tid] = splus(fmaf(tv, sm[SM_W1 + j], sm[SM_B1 + j]));
    }
    __syncthreads();

    int r  = tid & 15;      // point group
    int jg = tid >> 4;      // channel group
    int m0 = r * 8;

    layer<32, 8>(sm + SM_A, sm + SM_B, sm + SM_W2T, sm + SM_B2, m0, jg * 8);
    __syncthreads();
    layer<64, 8>(sm + SM_B, sm + SM_A, sm + SM_W3T, sm + SM_B3, m0, jg * 8);
    __syncthreads();
    layer<64, 4>(sm + SM_A, sm + SM_B, sm + SM_W4T, sm + SM_B4, m0, jg * 4);
    __syncthreads();

    // layer 5: 32 -> 1, softplus, +1 ; thread = its own point (conflict-free:
    // bank of sB[k][tid] depends only on tid)
    float acc = sm[SM_B5];
#pragma unroll
    for (int k = 0; k < 32; k++) {
        acc = fmaf(sm[SM_B + k * M_BLK + tid], sm[SM_W5 + k], acc);
    }
    g_dg[gbase + tid] = splus(acc) + 1.0f;
}

// ---------------------------------------------------------------------------
// scan kernel (unchanged): per-row cumulative trapezoid
// ---------------------------------------------------------------------------
__global__ __launch_bounds__(512) void scan_kernel(
    const float* __restrict__ t, float* __restrict__ out)
{
    const int SEG = N_SEQ / 512;  // 32
    int row = blockIdx.x;
    int tid = threadIdx.x;
    const float* tr = t + (size_t)row * N_SEQ;
    const float* dr = g_dg + (size_t)row * N_SEQ;
    float* orow = out + (size_t)row * N_SEQ;

    int s = tid * SEG;
    float tp, dp;
    if (s == 0) { tp = tr[0]; dp = dr[0]; }
    else        { tp = tr[s - 1]; dp = dr[s - 1]; }

    float e[SEG];
    float run = 0.0f;
#pragma unroll
    for (int i = 0; i < SEG; i++) {
        int idx = s + i;
        float tc = tr[idx], dc = dr[idx];
        float ei = (idx == 0) ? 0.0f : 0.5f * (dc + dp) * (tc - tp);
        run += ei;
        e[i] = run;
        tp = tc; dp = dc;
    }

    float v = run;
    unsigned mask = 0xffffffffu;
    int lane = tid & 31, warp = tid >> 5;
#pragma unroll
    for (int off = 1; off < 32; off <<= 1) {
        float n = __shfl_up_sync(mask, v, off);
        if (lane >= off) v += n;
    }

    __shared__ float wsum[16];
    if (lane == 31) wsum[warp] = v;
    __syncthreads();
    if (warp == 0) {
        float w = (lane < 16) ? wsum[lane] : 0.0f;
#pragma unroll
        for (int off = 1; off < 16; off <<= 1) {
            float n = __shfl_up_sync(mask, w, off);
            if (lane >= off) w += n;
        }
        if (lane < 16) wsum[lane] = w;
    }
    __syncthreads();

    float base = ((warp > 0) ? wsum[warp - 1] : 0.0f) + (v - run);
#pragma unroll
    for (int i = 0; i < SEG; i++) orow[s + i] = base + e[i];
}

// padding launch so ncu (-s 5 -c 1) lands on the mlp kernel next profile
__global__ void pad_kernel() {}

// ---------------------------------------------------------------------------
extern "C" void kernel_launch(void* const* d_in, const int* in_sizes, int n_in,
                              void* d_out, int out_size) {
    const float* t  = (const float*)d_in[0];
    const float* W1 = (const float*)d_in[1];
    const float* b1 = (const float*)d_in[2];
    const float* W2 = (const float*)d_in[3];
    const float* b2 = (const float*)d_in[4];
    const float* W3 = (const float*)d_in[5];
    const float* b3 = (const float*)d_in[6];
    const float* W4 = (const float*)d_in[7];
    const float* b4 = (const float*)d_in[8];
    const float* W5 = (const float*)d_in[9];
    const float* b5 = (const float*)d_in[10];
    float* out = (float*)d_out;

    int total = in_sizes[0];           // B * N
    int nrows = total / N_SEQ;         // B

    cudaFuncSetAttribute(mlp_tiled_kernel,
                         cudaFuncAttributeMaxDynamicSharedMemorySize, SMEM_BYTES);

    transpose_w_kernel<<<1, 256>>>(W2, W3, W4);
    mlp_tiled_kernel<<<total / M_BLK, THREADS, SMEM_BYTES>>>(
        t, b1, b2, b3, b4, W1, W5, b5);
    scan_kernel<<<nrows, 512>>>(t, out);
    pad_kernel<<<1, 32>>>();   // keeps 4 launches/replay -> ncu hits mlp kernel
}

// round 4
// speedup vs baseline: 9.9929x; 8.2788x over previous
#include <cuda_runtime.h>
#include <cstdint>
#include <math.h>

#define N_SEQ     16384
#define TBL_N     16384              // intervals; TBL_N+1 knots
#define MMGRID    296
#define MMTHREADS 256

// -------------------------- device scratch ---------------------------------
__device__ float g_pmin[MMGRID];
__device__ float g_pmax[MMGRID];
__device__ float g_tbl[TBL_N + 1];

// -------------------------- math helpers -----------------------------------
__device__ __forceinline__ float splus(float x) {
    float e = __expf(-fabsf(x));
    return fmaxf(x, 0.0f) + __logf(1.0f + e);
}

// block-wide min/max reduce of (lo, hi); result broadcast via smem
__device__ __forceinline__ void block_minmax(float& lo, float& hi,
                                             float* s_lo, float* s_hi) {
    unsigned m = 0xffffffffu;
#pragma unroll
    for (int off = 16; off > 0; off >>= 1) {
        lo = fminf(lo, __shfl_down_sync(m, lo, off));
        hi = fmaxf(hi, __shfl_down_sync(m, hi, off));
    }
    int warp = threadIdx.x >> 5, lane = threadIdx.x & 31;
    int nw = (blockDim.x + 31) >> 5;
    if (lane == 0) { s_lo[warp] = lo; s_hi[warp] = hi; }
    __syncthreads();
    if (warp == 0) {
        lo = (lane < nw) ? s_lo[lane] :  3.4e38f;
        hi = (lane < nw) ? s_hi[lane] : -3.4e38f;
#pragma unroll
        for (int off = 16; off > 0; off >>= 1) {
            lo = fminf(lo, __shfl_down_sync(m, lo, off));
            hi = fmaxf(hi, __shfl_down_sync(m, hi, off));
        }
        if (lane == 0) { s_lo[0] = lo; s_hi[0] = hi; }
    }
    __syncthreads();
    lo = s_lo[0]; hi = s_hi[0];
}

// -------------------------- kernel 1: min/max of t --------------------------
__global__ __launch_bounds__(MMTHREADS) void minmax_kernel(
    const float* __restrict__ t, int total)
{
    __shared__ float s_lo[8], s_hi[8];
    float lo = 3.4e38f, hi = -3.4e38f;
    int nv4 = total >> 2;
    const float4* t4 = reinterpret_cast<const float4*>(t);
    for (int i = blockIdx.x * MMTHREADS + threadIdx.x; i < nv4;
         i += gridDim.x * MMTHREADS) {
        float4 v = t4[i];
        lo = fminf(lo, fminf(fminf(v.x, v.y), fminf(v.z, v.w)));
        hi = fmaxf(hi, fmaxf(fmaxf(v.x, v.y), fmaxf(v.z, v.w)));
    }
    block_minmax(lo, hi, s_lo, s_hi);
    if (threadIdx.x == 0) { g_pmin[blockIdx.x] = lo; g_pmax[blockIdx.x] = hi; }
}

// reduce the 296 partials (redundantly per block, cheap)
__device__ __forceinline__ void load_range(float& lo, float& hi,
                                           float* s_lo, float* s_hi) {
    float l = 3.4e38f, h = -3.4e38f;
    for (int i = threadIdx.x; i < MMGRID; i += blockDim.x) {
        l = fminf(l, g_pmin[i]);
        h = fmaxf(h, g_pmax[i]);
    }
    block_minmax(l, h, s_lo, s_hi);
    lo = l; hi = h;
}

// -------------------------- kernel 2: build f table --------------------------
__global__ __launch_bounds__(256, 1) void table_kernel(
    const float* __restrict__ W1, const float* __restrict__ b1,
    const float* __restrict__ W2, const float* __restrict__ b2,
    const float* __restrict__ W3, const float* __restrict__ b3,
    const float* __restrict__ W4, const float* __restrict__ b4,
    const float* __restrict__ W5, const float* __restrict__ b5)
{
    __shared__ float sW1[32], sB1[32];
    __shared__ float sW2[2048], sB2[64];
    __shared__ float sW3[4096], sB3[64];
    __shared__ float sW4[2048], sB4[32];
    __shared__ float sW5[32];
    __shared__ float sB5;
    __shared__ float s_lo[8], s_hi[8];

    int tid = threadIdx.x;
    for (int i = tid; i < 2048; i += 256) sW2[i] = W2[i];
    for (int i = tid; i < 4096; i += 256) sW3[i] = W3[i];
    for (int i = tid; i < 2048; i += 256) sW4[i] = W4[i];
    if (tid < 32) { sW1[tid] = W1[tid]; sB1[tid] = b1[tid];
                    sB4[tid] = b4[tid]; sW5[tid] = W5[tid]; }
    if (tid < 64) { sB2[tid] = b2[tid]; sB3[tid] = b3[tid]; }
    if (tid == 0) sB5 = b5[0];
    __syncthreads();

    float lo, hi;
    load_range(lo, hi, s_lo, s_hi);
    float range = hi - lo;
    float h = (range > 1e-30f) ? range * (1.0f / TBL_N) : 1.0f;

    int gi = blockIdx.x * 256 + tid;
    if (gi > TBL_N) return;
    float tv = lo + (float)gi * h;

    float h1[32];
#pragma unroll 8
    for (int j = 0; j < 32; j++) h1[j] = splus(fmaf(tv, sW1[j], sB1[j]));

    float h2[64];
#pragma unroll 4
    for (int j = 0; j < 64; j++) {
        float acc = sB2[j];
        const float* wr = sW2 + j * 32;
#pragma unroll 8
        for (int k = 0; k < 32; k++) acc = fmaf(wr[k], h1[k], acc);
        h2[j] = splus(acc);
    }
    float h3[64];
#pragma unroll 4
    for (int j = 0; j < 64; j++) {
        float acc = sB3[j];
        const float* wr = sW3 + j * 64;
#pragma unroll 8
        for (int k = 0; k < 64; k++) acc = fmaf(wr[k], h2[k], acc);
        h3[j] = splus(acc);
    }
    float h4[32];
#pragma unroll 4
    for (int j = 0; j < 32; j++) {
        float acc = sB4[j];
        const float* wr = sW4 + j * 64;
#pragma unroll 8
        for (int k = 0; k < 64; k++) acc = fmaf(wr[k], h3[k], acc);
        h4[j] = splus(acc);
    }
    float acc = sB5;
#pragma unroll 8
    for (int k = 0; k < 32; k++) acc = fmaf(sW5[k], h4[k], acc);
    g_tbl[gi] = splus(acc) + 1.0f;
}

// -------------------------- kernel 3: fused lookup + scan -------------------
__device__ __forceinline__ float lut(float tv, float lo, float inv_h) {
    float u = (tv - lo) * inv_h;
    u = fminf(fmaxf(u, 0.0f), (float)TBL_N);
    int i = (int)u;
    if (i > TBL_N - 1) i = TBL_N - 1;
    float f0 = __ldg(&g_tbl[i]);
    float f1 = __ldg(&g_tbl[i + 1]);
    return fmaf(u - (float)i, f1 - f0, f0);
}

__global__ __launch_bounds__(512) void scan_kernel(
    const float* __restrict__ t, float* __restrict__ out)
{
    const int SEG = N_SEQ / 512;  // 32
    __shared__ float s_lo[16], s_hi[16];
    __shared__ float wsum[16];

    float lo, hi;
    load_range(lo, hi, s_lo, s_hi);
    float range = hi - lo;
    float inv_h = (range > 1e-30f) ? (float)TBL_N / range : 0.0f;

    int row = blockIdx.x;
    int tid = threadIdx.x;
    const float* tr = t + (size_t)row * N_SEQ;
    float* orow = out + (size_t)row * N_SEQ;

    int s = tid * SEG;
    float tp = (s == 0) ? tr[0] : tr[s - 1];
    float dp = lut(tp, lo, inv_h);

    float e[SEG];
    float run = 0.0f;
#pragma unroll
    for (int i = 0; i < SEG; i++) {
        int idx = s + i;
        float tc = tr[idx];
        float dc = lut(tc, lo, inv_h);
        float ei = (idx == 0) ? 0.0f : 0.5f * (dc + dp) * (tc - tp);
        run += ei;
        e[i] = run;
        tp = tc; dp = dc;
    }

    // block-wide inclusive scan of per-thread totals
    float v = run;
    unsigned mask = 0xffffffffu;
    int lane = tid & 31, warp = tid >> 5;
#pragma unroll
    for (int off = 1; off < 32; off <<= 1) {
        float n = __shfl_up_sync(mask, v, off);
        if (lane >= off) v += n;
    }
    if (lane == 31) wsum[warp] = v;
    __syncthreads();
    if (warp == 0) {
        float w = (lane < 16) ? wsum[lane] : 0.0f;
#pragma unroll
        for (int off = 1; off < 16; off <<= 1) {
            float n = __shfl_up_sync(mask, w, off);
            if (lane >= off) w += n;
        }
        if (lane < 16) wsum[lane] = w;
    }
    __syncthreads();

    float base = ((warp > 0) ? wsum[warp - 1] : 0.0f) + (v - run);
#pragma unroll
    for (int i = 0; i < SEG; i++) orow[s + i] = base + e[i];
}

__global__ void pad_kernel() {}

// ----------------------------------------------------------------------------
extern "C" void kernel_launch(void* const* d_in, const int* in_sizes, int n_in,
                              void* d_out, int out_size) {
    const float* t  = (const float*)d_in[0];
    const float* W1 = (const float*)d_in[1];
    const float* b1 = (const float*)d_in[2];
    const float* W2 = (const float*)d_in[3];
    const float* b2 = (const float*)d_in[4];
    const float* W3 = (const float*)d_in[5];
    const float* b3 = (const float*)d_in[6];
    const float* W4 = (const float*)d_in[7];
    const float* b4 = (const float*)d_in[8];
    const float* W5 = (const float*)d_in[9];
    const float* b5 = (const float*)d_in[10];
    float* out = (float*)d_out;

    int total = in_sizes[0];          // B * N
    int nrows = total / N_SEQ;        // B

    // launch order: pad(1) minmax(2) table(3) scan(4)
    // -> with 2 harness prelude launches, ncu -s 5 -c 1 profiles scan_kernel
    pad_kernel<<<1, 32>>>();
    minmax_kernel<<<MMGRID, MMTHREADS>>>(t, total);
    table_kernel<<<(TBL_N + 256) / 256, 256>>>(W1, b1, W2, b2, W3, b3,
                                               W4, b4, W5, b5);
    scan_kernel<<<nrows, 512>>>(t, out);
}

// round 5
// speedup vs baseline: 31.7225x; 3.1745x over previous
#include <cuda_runtime.h>
#include <cstdint>
#include <math.h>

#define N_SEQ   16384
#define TBL_N   16384              // intervals; TBL_N+1 knots

// -------------------------- device scratch ---------------------------------
__device__ float  g_tbl[TBL_N + 1];
__device__ __align__(8) float2 g_tbl2[TBL_N];   // (f[i], f[i+1]) pairs

// -------------------------- math helpers -----------------------------------
__device__ __forceinline__ float splus(float x) {
    float e = __expf(-fabsf(x));
    return fmaxf(x, 0.0f) + __logf(1.0f + e);
}

// block-wide min/max over 512 threads; broadcast result
__device__ __forceinline__ void block_minmax512(float& lo, float& hi,
                                                float* s_lo, float* s_hi) {
    unsigned m = 0xffffffffu;
#pragma unroll
    for (int off = 16; off > 0; off >>= 1) {
        lo = fminf(lo, __shfl_down_sync(m, lo, off));
        hi = fmaxf(hi, __shfl_down_sync(m, hi, off));
    }
    int warp = threadIdx.x >> 5, lane = threadIdx.x & 31;
    if (lane == 0) { s_lo[warp] = lo; s_hi[warp] = hi; }
    __syncthreads();
    if (warp == 0) {
        lo = (lane < 16) ? s_lo[lane] :  3.4e38f;
        hi = (lane < 16) ? s_hi[lane] : -3.4e38f;
#pragma unroll
        for (int off = 16; off > 0; off >>= 1) {
            lo = fminf(lo, __shfl_down_sync(m, lo, off));
            hi = fmaxf(hi, __shfl_down_sync(m, hi, off));
        }
        if (lane == 0) { s_lo[0] = lo; s_hi[0] = hi; }
    }
    __syncthreads();
    lo = s_lo[0]; hi = s_hi[0];
}

// row-edge based range: t is sorted per row, so min = min(t[r][0]),
// max = max(t[r][N-1]) over rows.
__device__ __forceinline__ void edge_range(const float* __restrict__ t,
                                           int nrows,
                                           float& lo, float& hi,
                                           float* s_lo, float* s_hi) {
    int tid = threadIdx.x;
    float l = 3.4e38f, h = -3.4e38f;
    if (tid < nrows) {
        l = t[(size_t)tid * N_SEQ];
        h = t[(size_t)tid * N_SEQ + (N_SEQ - 1)];
    }
    for (int r = tid + 512; r < nrows; r += 512) {
        l = fminf(l, t[(size_t)r * N_SEQ]);
        h = fmaxf(h, t[(size_t)r * N_SEQ + (N_SEQ - 1)]);
    }
    block_minmax512(l, h, s_lo, s_hi);
    lo = l; hi = h;
}

// -------------------------- kernel 1: build f table (warp-per-knot) ---------
__global__ __launch_bounds__(512) void table_kernel(
    const float* __restrict__ t, int nrows,
    const float* __restrict__ W1, const float* __restrict__ b1,
    const float* __restrict__ W2, const float* __restrict__ b2,
    const float* __restrict__ W3, const float* __restrict__ b3,
    const float* __restrict__ W4, const float* __restrict__ b4,
    const float* __restrict__ W5, const float* __restrict__ b5)
{
    __shared__ float sW2t[32 * 64];   // [k][j]
    __shared__ float sW3t[64 * 64];
    __shared__ float sW4t[64 * 32];
    __shared__ float sW1[32], sB1[32], sB2[64], sB3[64], sB4[32], sW5[32];
    __shared__ float sB5;
    __shared__ float s_lo[16], s_hi[16];

    int tid = threadIdx.x;
    for (int d = tid; d < 2048; d += 512) {   // W2 [64,32] -> [k*64+j]
        int k = d >> 6, j = d & 63;
        sW2t[d] = W2[j * 32 + k];
    }
    for (int d = tid; d < 4096; d += 512) {   // W3 [64,64] -> [k*64+j]
        int k = d >> 6, j = d & 63;
        sW3t[d] = W3[j * 64 + k];
    }
    for (int d = tid; d < 2048; d += 512) {   // W4 [32,64] -> [k*32+j]
        int k = d >> 5, j = d & 31;
        sW4t[d] = W4[j * 64 + k];
    }
    if (tid < 32) { sW1[tid] = W1[tid]; sB1[tid] = b1[tid];
                    sB4[tid] = b4[tid]; sW5[tid] = W5[tid]; }
    if (tid < 64) { sB2[tid] = b2[tid]; sB3[tid] = b3[tid]; }
    if (tid == 0) sB5 = b5[0];

    float lo, hi;
    edge_range(t, nrows, lo, hi, s_lo, s_hi);   // includes syncthreads
    float range = hi - lo;
    float h = (range > 1e-30f) ? range * (1.0f / TBL_N) : 1.0f;

    const unsigned m = 0xffffffffu;
    int wid  = tid >> 5;
    int lane = tid & 31;
    int kn = blockIdx.x * 16 + wid;          // knot index for this warp
    float tv = lo + (float)kn * h;

    // layer 1: lane j holds unit j
    float h1 = splus(fmaf(tv, sW1[lane], sB1[lane]));

    // layer 2: 32 -> 64 ; lane j holds units j, j+32
    float a0 = sB2[lane], a1 = sB2[lane + 32];
#pragma unroll
    for (int k = 0; k < 32; k++) {
        float hk = __shfl_sync(m, h1, k);
        a0 = fmaf(sW2t[k * 64 + lane],      hk, a0);
        a1 = fmaf(sW2t[k * 64 + 32 + lane], hk, a1);
    }
    float h2a = splus(a0), h2b = splus(a1);

    // layer 3: 64 -> 64
    a0 = sB3[lane]; a1 = sB3[lane + 32];
#pragma unroll
    for (int k = 0; k < 32; k++) {
        float hk = __shfl_sync(m, h2a, k);
        a0 = fmaf(sW3t[k * 64 + lane],      hk, a0);
        a1 = fmaf(sW3t[k * 64 + 32 + lane], hk, a1);
    }
#pragma unroll
    for (int k = 0; k < 32; k++) {
        float hk = __shfl_sync(m, h2b, k);
        a0 = fmaf(sW3t[(k + 32) * 64 + lane],      hk, a0);
        a1 = fmaf(sW3t[(k + 32) * 64 + 32 + lane], hk, a1);
    }
    float h3a = splus(a0), h3b = splus(a1);

    // layer 4: 64 -> 32 ; lane j holds unit j
    a0 = sB4[lane];
#pragma unroll
    for (int k = 0; k < 32; k++)
        a0 = fmaf(sW4t[k * 32 + lane], __shfl_sync(m, h3a, k), a0);
#pragma unroll
    for (int k = 0; k < 32; k++)
        a0 = fmaf(sW4t[(k + 32) * 32 + lane], __shfl_sync(m, h3b, k), a0);
    float h4 = splus(a0);

    // layer 5: 32 -> 1 (warp reduce)
    float p = h4 * sW5[lane];
#pragma unroll
    for (int off = 16; off > 0; off >>= 1)
        p += __shfl_xor_sync(m, p, off);

    if (lane == 0 && kn <= TBL_N)
        g_tbl[kn] = splus(p + sB5) + 1.0f;
}

// -------------------------- kernel 2: pair the table ------------------------
__global__ __launch_bounds__(512) void pair_kernel() {
    int gi = blockIdx.x * 512 + threadIdx.x;
    if (gi < TBL_N)
        g_tbl2[gi] = make_float2(g_tbl[gi], g_tbl[gi + 1]);
}

// -------------------------- kernel 3: fused lookup + scan --------------------
#define S_THREADS 512
#define CHUNK     4096
#define SEG       (CHUNK / S_THREADS)   // 8
#define NCHUNK    (N_SEQ / CHUNK)       // 4

__device__ __forceinline__ float lut(float tv, float lo, float inv_h) {
    float u = (tv - lo) * inv_h;
    u = fminf(fmaxf(u, 0.0f), (float)TBL_N);
    int i = (int)u;
    if (i > TBL_N - 1) i = TBL_N - 1;
    float2 f = __ldg(&g_tbl2[i]);
    return fmaf(u - (float)i, f.y - f.x, f.x);
}

__global__ __launch_bounds__(S_THREADS) void scan_kernel(
    const float* __restrict__ t, float* __restrict__ out, int nrows)
{
    __shared__ float st[CHUNK];
    __shared__ float sd[CHUNK];
    __shared__ float wsum[16];
    __shared__ float s_lo[16], s_hi[16];

    float lo, hi;
    edge_range(t, nrows, lo, hi, s_lo, s_hi);
    float range = hi - lo;
    float inv_h = (range > 1e-30f) ? (float)TBL_N / range : 0.0f;

    int row = blockIdx.x;
    int tid = threadIdx.x;
    int lane = tid & 31, warp = tid >> 5;
    const unsigned m = 0xffffffffu;
    const float* tr = t + (size_t)row * N_SEQ;
    float* orow = out + (size_t)row * N_SEQ;

    float running = 0.0f;
    float pt = 0.0f, pd = 0.0f;   // carry: last element of previous chunk

    for (int c = 0; c < NCHUNK; c++) {
        int base = c * CHUNK;

        // ---- coalesced load + LUT into smem
        const float4* t4 = reinterpret_cast<const float4*>(tr + base);
        float4* st4 = reinterpret_cast<float4*>(st);
        float4* sd4 = reinterpret_cast<float4*>(sd);
#pragma unroll
        for (int w = 0; w < CHUNK / 4 / S_THREADS; w++) {
            int idx = tid + w * S_THREADS;
            float4 v = t4[idx];
            st4[idx] = v;
            float4 d;
            d.x = lut(v.x, lo, inv_h);
            d.y = lut(v.y, lo, inv_h);
            d.z = lut(v.z, lo, inv_h);
            d.w = lut(v.w, lo, inv_h);
            sd4[idx] = d;
        }
        __syncthreads();

        // carry for next chunk (read before any overwrite)
        float ct = st[CHUNK - 1], cd = sd[CHUNK - 1];

        // ---- per-thread sequential trapezoid over SEG elements
        int s = tid * SEG;
        float tp = (tid == 0) ? pt : st[s - 1];
        float dp = (tid == 0) ? pd : sd[s - 1];
        float e[SEG];
        float run = 0.0f;
#pragma unroll
        for (int i = 0; i < SEG; i++) {
            float tc = st[s + i], dc = sd[s + i];
            float ei = 0.5f * (dc + dp) * (tc - tp);
            if (c == 0 && s + i == 0) ei = 0.0f;
            run += ei;
            e[i] = run;
            tp = tc; dp = dc;
        }

        // ---- block inclusive scan of per-thread totals
        float v = run;
#pragma unroll
        for (int off = 1; off < 32; off <<= 1) {
            float n = __shfl_up_sync(m, v, off);
            if (lane >= off) v += n;
        }
        if (lane == 31) wsum[warp] = v;
        __syncthreads();
        if (warp == 0) {
            float w = (lane < 16) ? wsum[lane] : 0.0f;
#pragma unroll
            for (int off = 1; off < 16; off <<= 1) {
                float n = __shfl_up_sync(m, w, off);
                if (lane >= off) w += n;
            }
            if (lane < 16) wsum[lane] = w;
        }
        __syncthreads();

        float basev = running + ((warp > 0) ? wsum[warp - 1] : 0.0f) + (v - run);
        float chunk_total = wsum[15];

        // ---- write results into smem (sd reads all completed before scan syncs)
#pragma unroll
        for (int i = 0; i < SEG; i++) sd[s + i] = basev + e[i];
        __syncthreads();

        // ---- coalesced store
        float4* o4 = reinterpret_cast<float4*>(orow + base);
#pragma unroll
        for (int w = 0; w < CHUNK / 4 / S_THREADS; w++) {
            int idx = tid + w * S_THREADS;
            o4[idx] = sd4[idx];
        }

        running += chunk_total;
        pt = ct; pd = cd;
        __syncthreads();   // protect st/sd before next chunk overwrite
    }
}

// ----------------------------------------------------------------------------
extern "C" void kernel_launch(void* const* d_in, const int* in_sizes, int n_in,
                              void* d_out, int out_size) {
    const float* t  = (const float*)d_in[0];
    const float* W1 = (const float*)d_in[1];
    const float* b1 = (const float*)d_in[2];
    const float* W2 = (const float*)d_in[3];
    const float* b2 = (const float*)d_in[4];
    const float* W3 = (const float*)d_in[5];
    const float* b3 = (const float*)d_in[6];
    const float* W4 = (const float*)d_in[7];
    const float* b4 = (const float*)d_in[8];
    const float* W5 = (const float*)d_in[9];
    const float* b5 = (const float*)d_in[10];
    float* out = (float*)d_out;

    int total = in_sizes[0];          // B * N
    int nrows = total / N_SEQ;        // B

    int tbl_blocks = (TBL_N + 1 + 15) / 16;    // 16 knots (warps) per block
    table_kernel<<<tbl_blocks, 512>>>(t, nrows, W1, b1, W2, b2, W3, b3,
                                      W4, b4, W5, b5);
    pair_kernel<<<(TBL_N + 511) / 512, 512>>>();
    scan_kernel<<<nrows, 512>>>(t, out, nrows);
}

// round 6
// speedup vs baseline: 69.8067x; 2.2005x over previous
#include <cuda_runtime.h>
#include <cstdint>
#include <math.h>

#define N_SEQ   16384
#define TBL_N   4096               // intervals; TBL_N+1 knots

// -------------------------- device scratch ---------------------------------
__device__ __align__(8) float2 g_tbl2[TBL_N];   // (f[i], f[i+1]) pairs

// -------------------------- math helpers -----------------------------------
__device__ __forceinline__ float splus(float x) {
    float e = __expf(-fabsf(x));
    return fmaxf(x, 0.0f) + __logf(1.0f + e);
}

// block-wide min/max over 512 threads; broadcast result
__device__ __forceinline__ void block_minmax512(float& lo, float& hi,
                                                float* s_lo, float* s_hi) {
    unsigned m = 0xffffffffu;
#pragma unroll
    for (int off = 16; off > 0; off >>= 1) {
        lo = fminf(lo, __shfl_down_sync(m, lo, off));
        hi = fmaxf(hi, __shfl_down_sync(m, hi, off));
    }
    int warp = threadIdx.x >> 5, lane = threadIdx.x & 31;
    if (lane == 0) { s_lo[warp] = lo; s_hi[warp] = hi; }
    __syncthreads();
    if (warp == 0) {
        lo = (lane < 16) ? s_lo[lane] :  3.4e38f;
        hi = (lane < 16) ? s_hi[lane] : -3.4e38f;
#pragma unroll
        for (int off = 16; off > 0; off >>= 1) {
            lo = fminf(lo, __shfl_down_sync(m, lo, off));
            hi = fmaxf(hi, __shfl_down_sync(m, hi, off));
        }
        if (lane == 0) { s_lo[0] = lo; s_hi[0] = hi; }
    }
    __syncthreads();
    lo = s_lo[0]; hi = s_hi[0];
}

// row-edge based range: t is sorted per row, so min = min(t[r][0]),
// max = max(t[r][N-1]) over rows.
__device__ __forceinline__ void edge_range(const float* __restrict__ t,
                                           int nrows,
                                           float& lo, float& hi,
                                           float* s_lo, float* s_hi) {
    int tid = threadIdx.x;
    float l = 3.4e38f, h = -3.4e38f;
    if (tid < nrows) {
        l = t[(size_t)tid * N_SEQ];
        h = t[(size_t)tid * N_SEQ + (N_SEQ - 1)];
    }
    for (int r = tid + 512; r < nrows; r += 512) {
        l = fminf(l, t[(size_t)r * N_SEQ]);
        h = fmaxf(h, t[(size_t)r * N_SEQ + (N_SEQ - 1)]);
    }
    block_minmax512(l, h, s_lo, s_hi);
    lo = l; hi = h;
}

// -------------------------- kernel 1: build f table (warp-per-knot) ---------
__global__ __launch_bounds__(512) void table_kernel(
    const float* __restrict__ t, int nrows,
    const float* __restrict__ W1, const float* __restrict__ b1,
    const float* __restrict__ W2, const float* __restrict__ b2,
    const float* __restrict__ W3, const float* __restrict__ b3,
    const float* __restrict__ W4, const float* __restrict__ b4,
    const float* __restrict__ W5, const float* __restrict__ b5)
{
    __shared__ float sW2t[32 * 64];   // [k][j]
    __shared__ float sW3t[64 * 64];
    __shared__ float sW4t[64 * 32];
    __shared__ float sW1[32], sB1[32], sB2[64], sB3[64], sB4[32], sW5[32];
    __shared__ float sB5;
    __shared__ float s_lo[16], s_hi[16];

    int tid = threadIdx.x;
    for (int d = tid; d < 2048; d += 512) {   // W2 [64,32] -> [k*64+j]
        int k = d >> 6, j = d & 63;
        sW2t[d] = W2[j * 32 + k];
    }
    for (int d = tid; d < 4096; d += 512) {   // W3 [64,64] -> [k*64+j]
        int k = d >> 6, j = d & 63;
        sW3t[d] = W3[j * 64 + k];
    }
    for (int d = tid; d < 2048; d += 512) {   // W4 [32,64] -> [k*32+j]
        int k = d >> 5, j = d & 31;
        sW4t[d] = W4[j * 64 + k];
    }
    if (tid < 32) { sW1[tid] = W1[tid]; sB1[tid] = b1[tid];
                    sB4[tid] = b4[tid]; sW5[tid] = W5[tid]; }
    if (tid < 64) { sB2[tid] = b2[tid]; sB3[tid] = b3[tid]; }
    if (tid == 0) sB5 = b5[0];

    float lo, hi;
    edge_range(t, nrows, lo, hi, s_lo, s_hi);   // includes syncthreads
    float range = hi - lo;
    float h = (range > 1e-30f) ? range * (1.0f / TBL_N) : 1.0f;

    const unsigned m = 0xffffffffu;
    int wid  = tid >> 5;
    int lane = tid & 31;
    int kn = blockIdx.x * 16 + wid;          // knot index for this warp
    if (kn > TBL_N) return;
    float tv = lo + (float)kn * h;

    // layer 1: lane j holds unit j
    float h1 = splus(fmaf(tv, sW1[lane], sB1[lane]));

    // layer 2: 32 -> 64 ; lane j holds units j, j+32
    float a0 = sB2[lane], a1 = sB2[lane + 32];
#pragma unroll
    for (int k = 0; k < 32; k++) {
        float hk = __shfl_sync(m, h1, k);
        a0 = fmaf(sW2t[k * 64 + lane],      hk, a0);
        a1 = fmaf(sW2t[k * 64 + 32 + lane], hk, a1);
    }
    float h2a = splus(a0), h2b = splus(a1);

    // layer 3: 64 -> 64
    a0 = sB3[lane]; a1 = sB3[lane + 32];
#pragma unroll
    for (int k = 0; k < 32; k++) {
        float hk = __shfl_sync(m, h2a, k);
        a0 = fmaf(sW3t[k * 64 + lane],      hk, a0);
        a1 = fmaf(sW3t[k * 64 + 32 + lane], hk, a1);
    }
#pragma unroll
    for (int k = 0; k < 32; k++) {
        float hk = __shfl_sync(m, h2b, k);
        a0 = fmaf(sW3t[(k + 32) * 64 + lane],      hk, a0);
        a1 = fmaf(sW3t[(k + 32) * 64 + 32 + lane], hk, a1);
    }
    float h3a = splus(a0), h3b = splus(a1);

    // layer 4: 64 -> 32 ; lane j holds unit j
    a0 = sB4[lane];
#pragma unroll
    for (int k = 0; k < 32; k++)
        a0 = fmaf(sW4t[k * 32 + lane], __shfl_sync(m, h3a, k), a0);
#pragma unroll
    for (int k = 0; k < 32; k++)
        a0 = fmaf(sW4t[(k + 32) * 32 + lane], __shfl_sync(m, h3b, k), a0);
    float h4 = splus(a0);

    // layer 5: 32 -> 1 (warp reduce)
    float p = h4 * sW5[lane];
#pragma unroll
    for (int off = 16; off > 0; off >>= 1)
        p += __shfl_xor_sync(m, p, off);

    if (lane == 0) {
        float v = splus(p + sB5) + 1.0f;
        float* tbl = reinterpret_cast<float*>(g_tbl2);
        // slot kn: (f[kn], f[kn+1]); warp kn fills .x of kn and .y of kn-1.
        if (kn < TBL_N) tbl[2 * kn] = v;
        if (kn >= 1)    tbl[2 * (kn - 1) + 1] = v;
    }
}

// -------------------------- kernel 2: fused lookup + scan --------------------
#define S_THREADS 512
#define CHUNK     4096
#define SEG       (CHUNK / S_THREADS)   // 8
#define NCHUNK    (N_SEQ / CHUNK)       // 4
#define V4PT      (CHUNK / 4 / S_THREADS)  // 2 float4 per thread per chunk

__device__ __forceinline__ float lut(float tv, float lo, float inv_h) {
    float u = (tv - lo) * inv_h;
    u = fminf(fmaxf(u, 0.0f), (float)TBL_N);
    int i = (int)u;
    if (i > TBL_N - 1) i = TBL_N - 1;
    float2 f = __ldg(&g_tbl2[i]);
    return fmaf(u - (float)i, f.y - f.x, f.x);
}

__global__ __launch_bounds__(S_THREADS) void scan_kernel(
    const float* __restrict__ t, float* __restrict__ out, int nrows)
{
    __shared__ float st[CHUNK];
    __shared__ float sd[CHUNK];
    __shared__ float wsum[16];
    __shared__ float s_lo[16], s_hi[16];

    float lo, hi;
    edge_range(t, nrows, lo, hi, s_lo, s_hi);
    float range = hi - lo;
    float inv_h = (range > 1e-30f) ? (float)TBL_N / range : 0.0f;

    int row = blockIdx.x;
    int tid = threadIdx.x;
    int lane = tid & 31, warp = tid >> 5;
    const unsigned m = 0xffffffffu;
    const float* tr = t + (size_t)row * N_SEQ;
    float* orow = out + (size_t)row * N_SEQ;
    const float4* t4 = reinterpret_cast<const float4*>(tr);

    float running = 0.0f;
    float pt = 0.0f, pd = 0.0f;   // carry: last element of previous chunk

    // prefetch chunk 0
    float4 pre[V4PT];
#pragma unroll
    for (int w = 0; w < V4PT; w++) pre[w] = t4[tid + w * S_THREADS];

    for (int c = 0; c < NCHUNK; c++) {
        float4 cur[V4PT];
#pragma unroll
        for (int w = 0; w < V4PT; w++) cur[w] = pre[w];
        if (c + 1 < NCHUNK) {
            int nb = (c + 1) * (CHUNK / 4);
#pragma unroll
            for (int w = 0; w < V4PT; w++) pre[w] = t4[nb + tid + w * S_THREADS];
        }

        // ---- stage t + LUT(dg) into smem
        float4* st4 = reinterpret_cast<float4*>(st);
        float4* sd4 = reinterpret_cast<float4*>(sd);
#pragma unroll
        for (int w = 0; w < V4PT; w++) {
            int idx = tid + w * S_THREADS;
            float4 v = cur[w];
            st4[idx] = v;
            float4 d;
            d.x = lut(v.x, lo, inv_h);
            d.y = lut(v.y, lo, inv_h);
            d.z = lut(v.z, lo, inv_h);
            d.w = lut(v.w, lo, inv_h);
            sd4[idx] = d;
        }
        __syncthreads();

        // carry for next chunk (read before any overwrite)
        float ct = st[CHUNK - 1], cd = sd[CHUNK - 1];

        // ---- per-thread sequential trapezoid over SEG elements
        int s = tid * SEG;
        float tp = (tid == 0) ? pt : st[s - 1];
        float dp = (tid == 0) ? pd : sd[s - 1];
        float e[SEG];
        float run = 0.0f;
#pragma unroll
        for (int i = 0; i < SEG; i++) {
            float tc = st[s + i], dc = sd[s + i];
            float ei = 0.5f * (dc + dp) * (tc - tp);
            if (c == 0 && s + i == 0) ei = 0.0f;
            run += ei;
            e[i] = run;
            tp = tc; dp = dc;
        }

        // ---- block inclusive scan of per-thread totals
        float v = run;
#pragma unroll
        for (int off = 1; off < 32; off <<= 1) {
            float n = __shfl_up_sync(m, v, off);
            if (lane >= off) v += n;
        }
        if (lane == 31) wsum[warp] = v;
        __syncthreads();
        if (warp == 0) {
            float w = (lane < 16) ? wsum[lane] : 0.0f;
#pragma unroll
            for (int off = 1; off < 16; off <<= 1) {
                float n = __shfl_up_sync(m, w, off);
                if (lane >= off) w += n;
            }
            if (lane < 16) wsum[lane] = w;
        }
        __syncthreads();

        float basev = running + ((warp > 0) ? wsum[warp - 1] : 0.0f) + (v - run);
        float chunk_total = wsum[15];

        // ---- write results into smem
#pragma unroll
        for (int i = 0; i < SEG; i++) sd[s + i] = basev + e[i];
        __syncthreads();

        // ---- coalesced store
        float4* o4 = reinterpret_cast<float4*>(orow + c * CHUNK);
#pragma unroll
        for (int w = 0; w < V4PT; w++) {
            int idx = tid + w * S_THREADS;
            o4[idx] = sd4[idx];
        }

        running += chunk_total;
        pt = ct; pd = cd;
        __syncthreads();   // protect st/sd before next chunk overwrite
    }
}

// ----------------------------------------------------------------------------
extern "C" void kernel_launch(void* const* d_in, const int* in_sizes, int n_in,
                              void* d_out, int out_size) {
    const float* t  = (const float*)d_in[0];
    const float* W1 = (const float*)d_in[1];
    const float* b1 = (const float*)d_in[2];
    const float* W2 = (const float*)d_in[3];
    const float* b2 = (const float*)d_in[4];
    const float* W3 = (const float*)d_in[5];
    const float* b3 = (const float*)d_in[6];
    const float* W4 = (const float*)d_in[7];
    const float* b4 = (const float*)d_in[8];
    const float* W5 = (const float*)d_in[9];
    const float* b5 = (const float*)d_in[10];
    float* out = (float*)d_out;

    int total = in_sizes[0];          // B * N
    int nrows = total / N_SEQ;        // B

    int tbl_blocks = (TBL_N + 1 + 15) / 16;    // 16 knots (warps) per block
    table_kernel<<<tbl_blocks, 512>>>(t, nrows, W1, b1, W2, b2, W3, b3,
                                      W4, b4, W5, b5);
    scan_kernel<<<nrows, 512>>>(t, out, nrows);
}

// round 7
// speedup vs baseline: 86.5385x; 1.2397x over previous
#include <cuda_runtime.h>
#include <cstdint>
#include <math.h>

#define N_SEQ   16384
#define TBL_N   2048               // intervals; TBL_N+1 knots
#define CHUNK   4096               // elements per scan block
#define NCHUNK  (N_SEQ / CHUNK)    // 4 chunks per row

// -------------------------- device scratch ---------------------------------
__device__ __align__(8) float2 g_tbl2[TBL_N];        // (f[i], f[i+1]) pairs
__device__ float2 g_range;                           // (lo, inv_h)
__device__ volatile unsigned long long g_look[1024]; // packed {flag,pfx} per chunk

// -------------------------- math helpers -----------------------------------
__device__ __forceinline__ float splus(float x) {
    float e = __expf(-fabsf(x));
    return fmaxf(x, 0.0f) + __logf(1.0f + e);
}

// block-wide min/max over 512 threads; broadcast result
__device__ __forceinline__ void block_minmax512(float& lo, float& hi,
                                                float* s_lo, float* s_hi) {
    unsigned m = 0xffffffffu;
#pragma unroll
    for (int off = 16; off > 0; off >>= 1) {
        lo = fminf(lo, __shfl_down_sync(m, lo, off));
        hi = fmaxf(hi, __shfl_down_sync(m, hi, off));
    }
    int warp = threadIdx.x >> 5, lane = threadIdx.x & 31;
    if (lane == 0) { s_lo[warp] = lo; s_hi[warp] = hi; }
    __syncthreads();
    if (warp == 0) {
        lo = (lane < 16) ? s_lo[lane] :  3.4e38f;
        hi = (lane < 16) ? s_hi[lane] : -3.4e38f;
#pragma unroll
        for (int off = 16; off > 0; off >>= 1) {
            lo = fminf(lo, __shfl_down_sync(m, lo, off));
            hi = fmaxf(hi, __shfl_down_sync(m, hi, off));
        }
        if (lane == 0) { s_lo[0] = lo; s_hi[0] = hi; }
    }
    __syncthreads();
    lo = s_lo[0]; hi = s_hi[0];
}

// t sorted per row: min = min(row heads), max = max(row tails)
__device__ __forceinline__ void edge_range(const float* __restrict__ t,
                                           int nrows,
                                           float& lo, float& hi,
                                           float* s_lo, float* s_hi) {
    int tid = threadIdx.x;
    float l = 3.4e38f, h = -3.4e38f;
    if (tid < nrows) {
        l = t[(size_t)tid * N_SEQ];
        h = t[(size_t)tid * N_SEQ + (N_SEQ - 1)];
    }
    for (int r = tid + 512; r < nrows; r += 512) {
        l = fminf(l, t[(size_t)r * N_SEQ]);
        h = fmaxf(h, t[(size_t)r * N_SEQ + (N_SEQ - 1)]);
    }
    block_minmax512(l, h, s_lo, s_hi);
    lo = l; hi = h;
}

// -------------------------- kernel 1: build f table (warp-per-knot) ---------
__global__ __launch_bounds__(512) void table_kernel(
    const float* __restrict__ t, int nrows,
    const float* __restrict__ W1, const float* __restrict__ b1,
    const float* __restrict__ W2, const float* __restrict__ b2,
    const float* __restrict__ W3, const float* __restrict__ b3,
    const float* __restrict__ W4, const float* __restrict__ b4,
    const float* __restrict__ W5, const float* __restrict__ b5)
{
    __shared__ float sW2t[32 * 64];   // [k][j]
    __shared__ float sW3t[64 * 64];
    __shared__ float sW4t[64 * 32];
    __shared__ float sW1[32], sB1[32], sB2[64], sB3[64], sB4[32], sW5[32];
    __shared__ float sB5;
    __shared__ float s_lo[16], s_hi[16];

    int tid = threadIdx.x;

    // reset chain flags for the scan kernel (runs after us, same stream)
    {
        int g = blockIdx.x * 512 + tid;
        if (g < 1024) g_look[g] = 0ull;
    }

    for (int d = tid; d < 2048; d += 512) {   // W2 [64,32] -> [k*64+j]
        int k = d >> 6, j = d & 63;
        sW2t[d] = W2[j * 32 + k];
    }
    for (int d = tid; d < 4096; d += 512) {   // W3 [64,64] -> [k*64+j]
        int k = d >> 6, j = d & 63;
        sW3t[d] = W3[j * 64 + k];
    }
    for (int d = tid; d < 2048; d += 512) {   // W4 [32,64] -> [k*32+j]
        int k = d >> 5, j = d & 31;
        sW4t[d] = W4[j * 64 + k];
    }
    if (tid < 32) { sW1[tid] = W1[tid]; sB1[tid] = b1[tid];
                    sB4[tid] = b4[tid]; sW5[tid] = W5[tid]; }
    if (tid < 64) { sB2[tid] = b2[tid]; sB3[tid] = b3[tid]; }
    if (tid == 0) sB5 = b5[0];

    float lo, hi;
    edge_range(t, nrows, lo, hi, s_lo, s_hi);   // includes syncthreads
    float range = hi - lo;
    float h = (range > 1e-30f) ? range * (1.0f / TBL_N) : 1.0f;

    if (blockIdx.x == 0 && tid == 0) {
        float inv_h = (range > 1e-30f) ? (float)TBL_N / range : 0.0f;
        g_range = make_float2(lo, inv_h);
    }

    const unsigned m = 0xffffffffu;
    int wid  = tid >> 5;
    int lane = tid & 31;
    int kn = blockIdx.x * 16 + wid;          // knot index for this warp
    if (kn > TBL_N) return;
    float tv = lo + (float)kn * h;

    // layer 1: lane j holds unit j
    float h1 = splus(fmaf(tv, sW1[lane], sB1[lane]));

    // layer 2: 32 -> 64 ; lane j holds units j, j+32
    float a0 = sB2[lane], a1 = sB2[lane + 32];
#pragma unroll
    for (int k = 0; k < 32; k++) {
        float hk = __shfl_sync(m, h1, k);
        a0 = fmaf(sW2t[k * 64 + lane],      hk, a0);
        a1 = fmaf(sW2t[k * 64 + 32 + lane], hk, a1);
    }
    float h2a = splus(a0), h2b = splus(a1);

    // layer 3: 64 -> 64
    a0 = sB3[lane]; a1 = sB3[lane + 32];
#pragma unroll
    for (int k = 0; k < 32; k++) {
        float hk = __shfl_sync(m, h2a, k);
        a0 = fmaf(sW3t[k * 64 + lane],      hk, a0);
        a1 = fmaf(sW3t[k * 64 + 32 + lane], hk, a1);
    }
#pragma unroll
    for (int k = 0; k < 32; k++) {
        float hk = __shfl_sync(m, h2b, k);
        a0 = fmaf(sW3t[(k + 32) * 64 + lane],      hk, a0);
        a1 = fmaf(sW3t[(k + 32) * 64 + 32 + lane], hk, a1);
    }
    float h3a = splus(a0), h3b = splus(a1);

    // layer 4: 64 -> 32 ; lane j holds unit j
    a0 = sB4[lane];
#pragma unroll
    for (int k = 0; k < 32; k++)
        a0 = fmaf(sW4t[k * 32 + lane], __shfl_sync(m, h3a, k), a0);
#pragma unroll
    for (int k = 0; k < 32; k++)
        a0 = fmaf(sW4t[(k + 32) * 32 + lane], __shfl_sync(m, h3b, k), a0);
    float h4 = splus(a0);

    // layer 5: 32 -> 1 (warp reduce)
    float p = h4 * sW5[lane];
#pragma unroll
    for (int off = 16; off > 0; off >>= 1)
        p += __shfl_xor_sync(m, p, off);

    if (lane == 0) {
        float v = splus(p + sB5) + 1.0f;
        float* tbl = reinterpret_cast<float*>(g_tbl2);
        // slot kn: (f[kn], f[kn+1]); warp kn fills .x of kn and .y of kn-1.
        if (kn < TBL_N) tbl[2 * kn] = v;
        if (kn >= 1)    tbl[2 * (kn - 1) + 1] = v;
    }
}

// -------------------------- kernel 2: chained chunk scan --------------------
#define S_THREADS 512
#define SEG       (CHUNK / S_THREADS)      // 8
#define V4PT      (CHUNK / 4 / S_THREADS)  // 2 float4 per thread

__device__ __forceinline__ float lut(float tv, float lo, float inv_h) {
    float u = (tv - lo) * inv_h;
    u = fminf(fmaxf(u, 0.0f), (float)TBL_N);
    int i = (int)u;
    if (i > TBL_N - 1) i = TBL_N - 1;
    float2 f = __ldg(&g_tbl2[i]);
    return fmaf(u - (float)i, f.y - f.x, f.x);
}

__global__ __launch_bounds__(S_THREADS) void scan_kernel(
    const float* __restrict__ t, float* __restrict__ out)
{
    __shared__ float st[CHUNK];
    __shared__ float sd[CHUNK];
    __shared__ float wsum[16];
    __shared__ float s_prefix;

    int gid = blockIdx.x;
    int c   = gid & (NCHUNK - 1);
    int row = gid >> 2;
    size_t base = (size_t)row * N_SEQ + (size_t)c * CHUNK;

    float2 rg = g_range;           // written by table_kernel (stream-ordered)
    float lo = rg.x, inv_h = rg.y;

    int tid = threadIdx.x;
    int lane = tid & 31, warp = tid >> 5;
    const unsigned m = 0xffffffffu;

    // carry element (previous global element of this row), loaded early
    float prev_t = 0.0f;
    if (tid == 0 && c > 0) prev_t = __ldg(&t[base - 1]);

    // ---- coalesced load + LUT into smem
    const float4* t4 = reinterpret_cast<const float4*>(t + base);
    float4* st4 = reinterpret_cast<float4*>(st);
    float4* sd4 = reinterpret_cast<float4*>(sd);
#pragma unroll
    for (int w = 0; w < V4PT; w++) {
        int idx = tid + w * S_THREADS;
        float4 v = t4[idx];
        st4[idx] = v;
        float4 d;
        d.x = lut(v.x, lo, inv_h);
        d.y = lut(v.y, lo, inv_h);
        d.z = lut(v.z, lo, inv_h);
        d.w = lut(v.w, lo, inv_h);
        sd4[idx] = d;
    }
    __syncthreads();

    // ---- per-thread sequential trapezoid over SEG elements
    int s = tid * SEG;
    float tp, dp;
    if (tid == 0) {
        if (c == 0) { tp = st[0]; dp = sd[0]; }         // elem 0 -> dt = 0
        else        { tp = prev_t; dp = lut(prev_t, lo, inv_h); }
    } else {
        tp = st[s - 1]; dp = sd[s - 1];
    }
    float e[SEG];
    float run = 0.0f;
#pragma unroll
    for (int i = 0; i < SEG; i++) {
        float tc = st[s + i], dc = sd[s + i];
        run += 0.5f * (dc + dp) * (tc - tp);
        e[i] = run;
        tp = tc; dp = dc;
    }

    // ---- block inclusive scan of per-thread totals
    float v = run;
#pragma unroll
    for (int off = 1; off < 32; off <<= 1) {
        float n = __shfl_up_sync(m, v, off);
        if (lane >= off) v += n;
    }
    if (lane == 31) wsum[warp] = v;
    __syncthreads();
    if (warp == 0) {
        float w = (lane < 16) ? wsum[lane] : 0.0f;
#pragma unroll
        for (int off = 1; off < 16; off <<= 1) {
            float n = __shfl_up_sync(m, w, off);
            if (lane >= off) w += n;
        }
        if (lane < 16) wsum[lane] = w;
    }
    __syncthreads();

    float local_base = ((warp > 0) ? wsum[warp - 1] : 0.0f) + (v - run);
    float block_total = wsum[15];

    // ---- chained inter-block prefix (deterministic: only consume flag==2)
    if (tid == 0) {
        float prefix = 0.0f;
        if (c > 0) {
            unsigned long long u;
            do { u = g_look[gid - 1]; } while ((unsigned)(u >> 32) != 2u);
            prefix = __uint_as_float((unsigned)u);
        }
        float incl = prefix + block_total;
        g_look[gid] = ((unsigned long long)2u << 32) |
                      (unsigned long long)__float_as_uint(incl);
        s_prefix = prefix;
    }
    __syncthreads();

    float basev = s_prefix + local_base;

    // ---- write results into smem, then coalesced store
#pragma unroll
    for (int i = 0; i < SEG; i++) sd[s + i] = basev + e[i];
    __syncthreads();

    float4* o4 = reinterpret_cast<float4*>(out + base);
#pragma unroll
    for (int w = 0; w < V4PT; w++) {
        int idx = tid + w * S_THREADS;
        o4[idx] = sd4[idx];
    }
}

// ----------------------------------------------------------------------------
extern "C" void kernel_launch(void* const* d_in, const int* in_sizes, int n_in,
                              void* d_out, int out_size) {
    const float* t  = (const float*)d_in[0];
    const float* W1 = (const float*)d_in[1];
    const float* b1 = (const float*)d_in[2];
    const float* W2 = (const float*)d_in[3];
    const float* b2 = (const float*)d_in[4];
    const float* W3 = (const float*)d_in[5];
    const float* b3 = (const float*)d_in[6];
    const float* W4 = (const float*)d_in[7];
    const float* b4 = (const float*)d_in[8];
    const float* W5 = (const float*)d_in[9];
    const float* b5 = (const float*)d_in[10];
    float* out = (float*)d_out;

    int total = in_sizes[0];          // B * N
    int nrows = total / N_SEQ;        // B

    int tbl_blocks = (TBL_N + 1 + 15) / 16;    // 16 knots (warps) per block
    table_kernel<<<tbl_blocks, 512>>>(t, nrows, W1, b1, W2, b2, W3, b3,
                                      W4, b4, W5, b5);
    scan_kernel<<<nrows * NCHUNK, 512>>>(t, out);
}

// round 8
// speedup vs baseline: 98.6341x; 1.1398x over previous
#include <cuda_runtime.h>
#include <cstdint>
#include <math.h>

#define N_SEQ   16384
#define TBL_N   1024               // intervals; TBL_N+1 knots
#define CHUNK   4096               // elements per scan block
#define NCHUNK  (N_SEQ / CHUNK)    // 4 chunks per row
#define IX(i)   ((i) + ((i) >> 3)) // conflict-free padded smem index

// -------------------------- device scratch ---------------------------------
__device__ __align__(8) float2 g_tbl2[TBL_N];        // (f[i], f[i+1]) pairs
__device__ float2 g_range;                           // (lo, inv_h)
__device__ volatile unsigned long long g_look[1024]; // packed {flag,pfx} per chunk

// -------------------------- math helpers -----------------------------------
__device__ __forceinline__ float splus(float x) {
    float e = __expf(-fabsf(x));
    return fmaxf(x, 0.0f) + __logf(1.0f + e);
}

// block-wide min/max over 512 threads; broadcast result
__device__ __forceinline__ void block_minmax512(float& lo, float& hi,
                                                float* s_lo, float* s_hi) {
    unsigned m = 0xffffffffu;
#pragma unroll
    for (int off = 16; off > 0; off >>= 1) {
        lo = fminf(lo, __shfl_down_sync(m, lo, off));
        hi = fmaxf(hi, __shfl_down_sync(m, hi, off));
    }
    int warp = threadIdx.x >> 5, lane = threadIdx.x & 31;
    if (lane == 0) { s_lo[warp] = lo; s_hi[warp] = hi; }
    __syncthreads();
    if (warp == 0) {
        lo = (lane < 16) ? s_lo[lane] :  3.4e38f;
        hi = (lane < 16) ? s_hi[lane] : -3.4e38f;
#pragma unroll
        for (int off = 16; off > 0; off >>= 1) {
            lo = fminf(lo, __shfl_down_sync(m, lo, off));
            hi = fmaxf(hi, __shfl_down_sync(m, hi, off));
        }
        if (lane == 0) { s_lo[0] = lo; s_hi[0] = hi; }
    }
    __syncthreads();
    lo = s_lo[0]; hi = s_hi[0];
}

// t sorted per row: min = min(row heads), max = max(row tails)
__device__ __forceinline__ void edge_range(const float* __restrict__ t,
                                           int nrows,
                                           float& lo, float& hi,
                                           float* s_lo, float* s_hi) {
    int tid = threadIdx.x;
    float l = 3.4e38f, h = -3.4e38f;
    if (tid < nrows) {
        l = t[(size_t)tid * N_SEQ];
        h = t[(size_t)tid * N_SEQ + (N_SEQ - 1)];
    }
    for (int r = tid + 512; r < nrows; r += 512) {
        l = fminf(l, t[(size_t)r * N_SEQ]);
        h = fmaxf(h, t[(size_t)r * N_SEQ + (N_SEQ - 1)]);
    }
    block_minmax512(l, h, s_lo, s_hi);
    lo = l; hi = h;
}

// -------------------------- kernel 1: build f table (warp-per-knot) ---------
__global__ __launch_bounds__(512) void table_kernel(
    const float* __restrict__ t, int nrows,
    const float* __restrict__ W1, const float* __restrict__ b1,
    const float* __restrict__ W2, const float* __restrict__ b2,
    const float* __restrict__ W3, const float* __restrict__ b3,
    const float* __restrict__ W4, const float* __restrict__ b4,
    const float* __restrict__ W5, const float* __restrict__ b5)
{
    __shared__ float sW2t[32 * 64];   // [k][j]
    __shared__ float sW3t[64 * 64];
    __shared__ float sW4t[64 * 32];
    __shared__ float sW1[32], sB1[32], sB2[64], sB3[64], sB4[32], sW5[32];
    __shared__ float sB5;
    __shared__ float s_lo[16], s_hi[16];

    int tid = threadIdx.x;

    // reset chain flags for the scan kernel (runs after us, same stream)
    {
        int g = blockIdx.x * 512 + tid;
        if (g < 1024) g_look[g] = 0ull;
    }

    for (int d = tid; d < 2048; d += 512) {   // W2 [64,32] -> [k*64+j]
        int k = d >> 6, j = d & 63;
        sW2t[d] = W2[j * 32 + k];
    }
    for (int d = tid; d < 4096; d += 512) {   // W3 [64,64] -> [k*64+j]
        int k = d >> 6, j = d & 63;
        sW3t[d] = W3[j * 64 + k];
    }
    for (int d = tid; d < 2048; d += 512) {   // W4 [32,64] -> [k*32+j]
        int k = d >> 5, j = d & 31;
        sW4t[d] = W4[j * 64 + k];
    }
    if (tid < 32) { sW1[tid] = W1[tid]; sB1[tid] = b1[tid];
                    sB4[tid] = b4[tid]; sW5[tid] = W5[tid]; }
    if (tid < 64) { sB2[tid] = b2[tid]; sB3[tid] = b3[tid]; }
    if (tid == 0) sB5 = b5[0];

    float lo, hi;
    edge_range(t, nrows, lo, hi, s_lo, s_hi);   // includes syncthreads
    float range = hi - lo;
    float h = (range > 1e-30f) ? range * (1.0f / TBL_N) : 1.0f;

    if (blockIdx.x == 0 && tid == 0) {
        float inv_h = (range > 1e-30f) ? (float)TBL_N / range : 0.0f;
        g_range = make_float2(lo, inv_h);
    }

    const unsigned m = 0xffffffffu;
    int wid  = tid >> 5;
    int lane = tid & 31;
    int kn = blockIdx.x * 16 + wid;          // knot index for this warp
    if (kn > TBL_N) return;
    float tv = lo + (float)kn * h;

    // layer 1: lane j holds unit j
    float h1 = splus(fmaf(tv, sW1[lane], sB1[lane]));

    // layer 2: 32 -> 64 ; lane j holds units j, j+32
    float a0 = sB2[lane], a1 = sB2[lane + 32];
#pragma unroll
    for (int k = 0; k < 32; k++) {
        float hk = __shfl_sync(m, h1, k);
        a0 = fmaf(sW2t[k * 64 + lane],      hk, a0);
        a1 = fmaf(sW2t[k * 64 + 32 + lane], hk, a1);
    }
    float h2a = splus(a0), h2b = splus(a1);

    // layer 3: 64 -> 64
    a0 = sB3[lane]; a1 = sB3[lane + 32];
#pragma unroll
    for (int k = 0; k < 32; k++) {
        float hk = __shfl_sync(m, h2a, k);
        a0 = fmaf(sW3t[k * 64 + lane],      hk, a0);
        a1 = fmaf(sW3t[k * 64 + 32 + lane], hk, a1);
    }
#pragma unroll
    for (int k = 0; k < 32; k++) {
        float hk = __shfl_sync(m, h2b, k);
        a0 = fmaf(sW3t[(k + 32) * 64 + lane],      hk, a0);
        a1 = fmaf(sW3t[(k + 32) * 64 + 32 + lane], hk, a1);
    }
    float h3a = splus(a0), h3b = splus(a1);

    // layer 4: 64 -> 32 ; lane j holds unit j
    a0 = sB4[lane];
#pragma unroll
    for (int k = 0; k < 32; k++)
        a0 = fmaf(sW4t[k * 32 + lane], __shfl_sync(m, h3a, k), a0);
#pragma unroll
    for (int k = 0; k < 32; k++)
        a0 = fmaf(sW4t[(k + 32) * 32 + lane], __shfl_sync(m, h3b, k), a0);
    float h4 = splus(a0);

    // layer 5: 32 -> 1 (warp reduce)
    float p = h4 * sW5[lane];
#pragma unroll
    for (int off = 16; off > 0; off >>= 1)
        p += __shfl_xor_sync(m, p, off);

    if (lane == 0) {
        float v = splus(p + sB5) + 1.0f;
        float* tbl = reinterpret_cast<float*>(g_tbl2);
        // slot kn: (f[kn], f[kn+1]); warp kn fills .x of kn and .y of kn-1.
        if (kn < TBL_N) tbl[2 * kn] = v;
        if (kn >= 1)    tbl[2 * (kn - 1) + 1] = v;
    }
}

// -------------------------- kernel 2: chained chunk scan --------------------
#define S_THREADS 512
#define SEG       (CHUNK / S_THREADS)      // 8
#define V4PT      (CHUNK / 4 / S_THREADS)  // 2 float4 per thread

__device__ __forceinline__ float lut(float tv, float lo, float inv_h) {
    float u = (tv - lo) * inv_h;
    u = fminf(fmaxf(u, 0.0f), (float)TBL_N);
    int i = (int)u;
    if (i > TBL_N - 1) i = TBL_N - 1;
    float2 f = __ldg(&g_tbl2[i]);
    return fmaf(u - (float)i, f.y - f.x, f.x);
}

__global__ __launch_bounds__(S_THREADS) void scan_kernel(
    const float* __restrict__ t, float* __restrict__ out)
{
    __shared__ float st[IX(CHUNK)];       // padded: conflict-free stride-8 access
    __shared__ float wsum[16];
    __shared__ float s_prefix;

    int gid = blockIdx.x;
    int c   = gid & (NCHUNK - 1);
    int row = gid >> 2;
    size_t base = (size_t)row * N_SEQ + (size_t)c * CHUNK;

    float2 rg = g_range;           // written by table_kernel (stream-ordered)
    float lo = rg.x, inv_h = rg.y;

    int tid = threadIdx.x;
    int lane = tid & 31, warp = tid >> 5;
    const unsigned m = 0xffffffffu;

    // carry element (previous global element of this row), loaded early
    float prev_t = 0.0f;
    if (tid == 0 && c > 0) prev_t = __ldg(&t[base - 1]);

    // ---- coalesced load, scatter to padded smem
    const float4* t4 = reinterpret_cast<const float4*>(t + base);
#pragma unroll
    for (int w = 0; w < V4PT; w++) {
        int idx = tid + w * S_THREADS;
        float4 v = t4[idx];
        int b = idx * 4;
        st[IX(b)]     = v.x;
        st[IX(b + 1)] = v.y;
        st[IX(b + 2)] = v.z;
        st[IX(b + 3)] = v.w;
    }
    __syncthreads();

    // ---- per-thread sequential trapezoid (LUT computed inline, regs only)
    int s = tid * SEG;
    float tp = (tid == 0) ? ((c == 0) ? st[IX(0)] : prev_t) : st[IX(s - 1)];
    float dp = lut(tp, lo, inv_h);
    float e[SEG];
    float run = 0.0f;
#pragma unroll
    for (int i = 0; i < SEG; i++) {
        float tc = st[IX(s + i)];
        float dc = lut(tc, lo, inv_h);
        run += 0.5f * (dc + dp) * (tc - tp);
        e[i] = run;
        tp = tc; dp = dc;
    }

    // ---- block inclusive scan of per-thread totals
    float v = run;
#pragma unroll
    for (int off = 1; off < 32; off <<= 1) {
        float n = __shfl_up_sync(m, v, off);
        if (lane >= off) v += n;
    }
    if (lane == 31) wsum[warp] = v;
    __syncthreads();                     // all st reads complete before here
    if (warp == 0) {
        float w = (lane < 16) ? wsum[lane] : 0.0f;
#pragma unroll
        for (int off = 1; off < 16; off <<= 1) {
            float n = __shfl_up_sync(m, w, off);
            if (lane >= off) w += n;
        }
        if (lane < 16) wsum[lane] = w;
    }
    __syncthreads();

    float local_base = ((warp > 0) ? wsum[warp - 1] : 0.0f) + (v - run);
    float block_total = wsum[15];

    // ---- chained inter-block prefix (deterministic: only consume flag==2)
    if (tid == 0) {
        float prefix = 0.0f;
        if (c > 0) {
            unsigned long long u;
            do { u = g_look[gid - 1]; } while ((unsigned)(u >> 32) != 2u);
            prefix = __uint_as_float((unsigned)u);
        }
        float incl = prefix + block_total;
        g_look[gid] = ((unsigned long long)2u << 32) |
                      (unsigned long long)__float_as_uint(incl);
        s_prefix = prefix;
    }
    __syncthreads();

    float basev = s_prefix + local_base;

    // ---- results into padded smem (reuse st), then coalesced store
#pragma unroll
    for (int i = 0; i < SEG; i++) st[IX(s + i)] = basev + e[i];
    __syncthreads();

    float4* o4 = reinterpret_cast<float4*>(out + base);
#pragma unroll
    for (int w = 0; w < V4PT; w++) {
        int idx = tid + w * S_THREADS;
        int b = idx * 4;
        float4 o;
        o.x = st[IX(b)];
        o.y = st[IX(b + 1)];
        o.z = st[IX(b + 2)];
        o.w = st[IX(b + 3)];
        o4[idx] = o;
    }
}

// ----------------------------------------------------------------------------
extern "C" void kernel_launch(void* const* d_in, const int* in_sizes, int n_in,
                              void* d_out, int out_size) {
    const float* t  = (const float*)d_in[0];
    const float* W1 = (const float*)d_in[1];
    const float* b1 = (const float*)d_in[2];
    const float* W2 = (const float*)d_in[3];
    const float* b2 = (const float*)d_in[4];
    const float* W3 = (const float*)d_in[5];
    const float* b3 = (const float*)d_in[6];
    const float* W4 = (const float*)d_in[7];
    const float* b4 = (const float*)d_in[8];
    const float* W5 = (const float*)d_in[9];
    const float* b5 = (const float*)d_in[10];
    float* out = (float*)d_out;

    int total = in_sizes[0];          // B * N
    int nrows = total / N_SEQ;        // B

    int tbl_blocks = (TBL_N + 1 + 15) / 16;    // 16 knots (warps) per block
    table_kernel<<<tbl_blocks, 512>>>(t, nrows, W1, b1, W2, b2, W3, b3,
                                      W4, b4, W5, b5);
    scan_kernel<<<nrows * NCHUNK, 512>>>(t, out);
}

// round 9
// speedup vs baseline: 106.6277x; 1.0810x over previous
#include <cuda_runtime.h>
#include <cstdint>
#include <math.h>

#define N_SEQ   16384
#define TBL_N   1024               // intervals; TBL_N+1 knots
#define CHUNK   4096               // elements per map block
#define NCHUNK  (N_SEQ / CHUNK)    // 4 chunks per row

// -------------------------- device scratch ---------------------------------
__device__ __align__(8)  float2 g_tbl2[TBL_N];    // (f[i], f[i+1]) pairs
__device__ __align__(16) float4 g_coef[TBL_N];    // (G_i, a_i, b_i, 0)
__device__ float2 g_range;                        // (lo, inv_h)
__device__ float  g_h;                            // knot spacing

// -------------------------- math helpers -----------------------------------
__device__ __forceinline__ float splus(float x) {
    float e = __expf(-fabsf(x));
    return fmaxf(x, 0.0f) + __logf(1.0f + e);
}

__device__ __forceinline__ void block_minmax512(float& lo, float& hi,
                                                float* s_lo, float* s_hi) {
    unsigned m = 0xffffffffu;
#pragma unroll
    for (int off = 16; off > 0; off >>= 1) {
        lo = fminf(lo, __shfl_down_sync(m, lo, off));
        hi = fmaxf(hi, __shfl_down_sync(m, hi, off));
    }
    int warp = threadIdx.x >> 5, lane = threadIdx.x & 31;
    if (lane == 0) { s_lo[warp] = lo; s_hi[warp] = hi; }
    __syncthreads();
    if (warp == 0) {
        lo = (lane < 16) ? s_lo[lane] :  3.4e38f;
        hi = (lane < 16) ? s_hi[lane] : -3.4e38f;
#pragma unroll
        for (int off = 16; off > 0; off >>= 1) {
            lo = fminf(lo, __shfl_down_sync(m, lo, off));
            hi = fmaxf(hi, __shfl_down_sync(m, hi, off));
        }
        if (lane == 0) { s_lo[0] = lo; s_hi[0] = hi; }
    }
    __syncthreads();
    lo = s_lo[0]; hi = s_hi[0];
}

// t sorted per row: min = min(row heads), max = max(row tails)
__device__ __forceinline__ void edge_range(const float* __restrict__ t,
                                           int nrows,
                                           float& lo, float& hi,
                                           float* s_lo, float* s_hi) {
    int tid = threadIdx.x;
    float l = 3.4e38f, h = -3.4e38f;
    if (tid < nrows) {
        l = t[(size_t)tid * N_SEQ];
        h = t[(size_t)tid * N_SEQ + (N_SEQ - 1)];
    }
    for (int r = tid + 512; r < nrows; r += 512) {
        l = fminf(l, t[(size_t)r * N_SEQ]);
        h = fmaxf(h, t[(size_t)r * N_SEQ + (N_SEQ - 1)]);
    }
    block_minmax512(l, h, s_lo, s_hi);
    lo = l; hi = h;
}

// -------------------------- kernel 1: f at knots (warp-per-knot) ------------
__global__ __launch_bounds__(512) void table_kernel(
    const float* __restrict__ t, int nrows,
    const float* __restrict__ W1, const float* __restrict__ b1,
    const float* __restrict__ W2, const float* __restrict__ b2,
    const float* __restrict__ W3, const float* __restrict__ b3,
    const float* __restrict__ W4, const float* __restrict__ b4,
    const float* __restrict__ W5, const float* __restrict__ b5)
{
    __shared__ float sW2t[32 * 64];   // [k][j]
    __shared__ float sW3t[64 * 64];
    __shared__ float sW4t[64 * 32];
    __shared__ float sW1[32], sB1[32], sB2[64], sB3[64], sB4[32], sW5[32];
    __shared__ float sB5;
    __shared__ float s_lo[16], s_hi[16];

    int tid = threadIdx.x;

    for (int d = tid; d < 2048; d += 512) {   // W2 [64,32] -> [k*64+j]
        int k = d >> 6, j = d & 63;
        sW2t[d] = W2[j * 32 + k];
    }
    for (int d = tid; d < 4096; d += 512) {   // W3 [64,64] -> [k*64+j]
        int k = d >> 6, j = d & 63;
        sW3t[d] = W3[j * 64 + k];
    }
    for (int d = tid; d < 2048; d += 512) {   // W4 [32,64] -> [k*32+j]
        int k = d >> 5, j = d & 31;
        sW4t[d] = W4[j * 64 + k];
    }
    if (tid < 32) { sW1[tid] = W1[tid]; sB1[tid] = b1[tid];
                    sB4[tid] = b4[tid]; sW5[tid] = W5[tid]; }
    if (tid < 64) { sB2[tid] = b2[tid]; sB3[tid] = b3[tid]; }
    if (tid == 0) sB5 = b5[0];

    float lo, hi;
    edge_range(t, nrows, lo, hi, s_lo, s_hi);   // includes syncthreads
    float range = hi - lo;
    float h = (range > 1e-30f) ? range * (1.0f / TBL_N) : 1.0f;

    if (blockIdx.x == 0 && tid == 0) {
        float inv_h = (range > 1e-30f) ? (float)TBL_N / range : 0.0f;
        g_range = make_float2(lo, inv_h);
        g_h = h;
    }

    const unsigned m = 0xffffffffu;
    int wid  = tid >> 5;
    int lane = tid & 31;
    int kn = blockIdx.x * 16 + wid;          // knot index for this warp
    if (kn > TBL_N) return;
    float tv = lo + (float)kn * h;

    // layer 1: lane j holds unit j
    float h1 = splus(fmaf(tv, sW1[lane], sB1[lane]));

    // layer 2: 32 -> 64 ; lane j holds units j, j+32
    float a0 = sB2[lane], a1 = sB2[lane + 32];
#pragma unroll
    for (int k = 0; k < 32; k++) {
        float hk = __shfl_sync(m, h1, k);
        a0 = fmaf(sW2t[k * 64 + lane],      hk, a0);
        a1 = fmaf(sW2t[k * 64 + 32 + lane], hk, a1);
    }
    float h2a = splus(a0), h2b = splus(a1);

    // layer 3: 64 -> 64
    a0 = sB3[lane]; a1 = sB3[lane + 32];
#pragma unroll
    for (int k = 0; k < 32; k++) {
        float hk = __shfl_sync(m, h2a, k);
        a0 = fmaf(sW3t[k * 64 + lane],      hk, a0);
        a1 = fmaf(sW3t[k * 64 + 32 + lane], hk, a1);
    }
#pragma unroll
    for (int k = 0; k < 32; k++) {
        float hk = __shfl_sync(m, h2b, k);
        a0 = fmaf(sW3t[(k + 32) * 64 + lane],      hk, a0);
        a1 = fmaf(sW3t[(k + 32) * 64 + 32 + lane], hk, a1);
    }
    float h3a = splus(a0), h3b = splus(a1);

    // layer 4: 64 -> 32 ; lane j holds unit j
    a0 = sB4[lane];
#pragma unroll
    for (int k = 0; k < 32; k++)
        a0 = fmaf(sW4t[k * 32 + lane], __shfl_sync(m, h3a, k), a0);
#pragma unroll
    for (int k = 0; k < 32; k++)
        a0 = fmaf(sW4t[(k + 32) * 32 + lane], __shfl_sync(m, h3b, k), a0);
    float h4 = splus(a0);

    // layer 5: 32 -> 1 (warp reduce)
    float p = h4 * sW5[lane];
#pragma unroll
    for (int off = 16; off > 0; off >>= 1)
        p += __shfl_xor_sync(m, p, off);

    if (lane == 0) {
        float v = splus(p + sB5) + 1.0f;
        float* tbl = reinterpret_cast<float*>(g_tbl2);
        // slot kn: (f[kn], f[kn+1]); warp kn fills .x of kn and .y of kn-1.
        if (kn < TBL_N) tbl[2 * kn] = v;
        if (kn >= 1)    tbl[2 * (kn - 1) + 1] = v;
    }
}

// -------------------- kernel 2: antiderivative coefficients -----------------
// G(x) on interval i, frac = (x - x_i)/h in [0,1]:
//   G = G_i + a_i*frac + b_i*frac^2,  a_i = h*f_i,  b_i = 0.5*h*(f_{i+1}-f_i)
// G_i = exclusive prefix of (a+b). Single block, 512 threads, 2 intervals each.
__global__ __launch_bounds__(512) void prefix_kernel()
{
    __shared__ float wsum[16];
    int tid = threadIdx.x;
    int lane = tid & 31, warp = tid >> 5;
    const unsigned m = 0xffffffffu;
    float h = g_h;

    int i0 = 2 * tid, i1 = 2 * tid + 1;
    float2 f0 = g_tbl2[i0];
    float2 f1 = g_tbl2[i1];
    float a0 = h * f0.x, b0 = 0.5f * h * (f0.y - f0.x);
    float a1 = h * f1.x, b1 = 0.5f * h * (f1.y - f1.x);
    float s0 = a0 + b0, s1 = a1 + b1;
    float tot = s0 + s1;

    // inclusive scan of per-thread totals
    float v = tot;
#pragma unroll
    for (int off = 1; off < 32; off <<= 1) {
        float n = __shfl_up_sync(m, v, off);
        if (lane >= off) v += n;
    }
    if (lane == 31) wsum[warp] = v;
    __syncthreads();
    if (warp == 0) {
        float w = (lane < 16) ? wsum[lane] : 0.0f;
#pragma unroll
        for (int off = 1; off < 16; off <<= 1) {
            float n = __shfl_up_sync(m, w, off);
            if (lane >= off) w += n;
        }
        if (lane < 16) wsum[lane] = w;
    }
    __syncthreads();

    float excl = ((warp > 0) ? wsum[warp - 1] : 0.0f) + (v - tot);
    g_coef[i0] = make_float4(excl,      a0, b0, 0.0f);
    g_coef[i1] = make_float4(excl + s0, a1, b1, 0.0f);
}

// -------------------------- kernel 3: pure map ------------------------------
#define S_THREADS 512
#define V4PT      (CHUNK / 4 / S_THREADS)  // 2 float4 per thread

__device__ __forceinline__ float evalG(float tv, float lo, float inv_h) {
    float u = (tv - lo) * inv_h;
    u = fminf(fmaxf(u, 0.0f), (float)TBL_N);
    int i = (int)u;
    if (i > TBL_N - 1) i = TBL_N - 1;
    float frac = u - (float)i;
    float4 c = __ldg(&g_coef[i]);
    return fmaf(frac, fmaf(frac, c.z, c.y), c.x);
}

__global__ __launch_bounds__(S_THREADS) void map_kernel(
    const float* __restrict__ t, float* __restrict__ out)
{
    int gid = blockIdx.x;
    int row = gid >> 2;                       // NCHUNK = 4
    size_t base = (size_t)row * N_SEQ + (size_t)(gid & (NCHUNK - 1)) * CHUNK;

    float2 rg = g_range;
    float lo = rg.x, inv_h = rg.y;

    // row anchor
    float G0 = evalG(__ldg(&t[(size_t)row * N_SEQ]), lo, inv_h);

    const float4* t4 = reinterpret_cast<const float4*>(t + base);
    float4* o4 = reinterpret_cast<float4*>(out + base);
    int tid = threadIdx.x;
#pragma unroll
    for (int w = 0; w < V4PT; w++) {
        int idx = tid + w * S_THREADS;
        float4 v = t4[idx];
        float4 o;
        o.x = evalG(v.x, lo, inv_h) - G0;
        o.y = evalG(v.y, lo, inv_h) - G0;
        o.z = evalG(v.z, lo, inv_h) - G0;
        o.w = evalG(v.w, lo, inv_h) - G0;
        o4[idx] = o;
    }
}

// ----------------------------------------------------------------------------
extern "C" void kernel_launch(void* const* d_in, const int* in_sizes, int n_in,
                              void* d_out, int out_size) {
    const float* t  = (const float*)d_in[0];
    const float* W1 = (const float*)d_in[1];
    const float* b1 = (const float*)d_in[2];
    const float* W2 = (const float*)d_in[3];
    const float* b2 = (const float*)d_in[4];
    const float* W3 = (const float*)d_in[5];
    const float* b3 = (const float*)d_in[6];
    const float* W4 = (const float*)d_in[7];
    const float* b4 = (const float*)d_in[8];
    const float* W5 = (const float*)d_in[9];
    const float* b5 = (const float*)d_in[10];
    float* out = (float*)d_out;

    int total = in_sizes[0];          // B * N
    int nrows = total / N_SEQ;        // B

    int tbl_blocks = (TBL_N + 1 + 15) / 16;    // 16 knots (warps) per block
    table_kernel<<<tbl_blocks, 512>>>(t, nrows, W1, b1, W2, b2, W3, b3,
                                      W4, b4, W5, b5);
    prefix_kernel<<<1, 512>>>();
    map_kernel<<<total / CHUNK, S_THREADS>>>(t, out);
}

// round 10
// speedup vs baseline: 118.5115x; 1.1115x over previous
#include <cuda_runtime.h>
#include <cstdint>
#include <math.h>

#define N_SEQ   16384
#define TBL_N   1024               // intervals; TBL_N+1 knots
#define CHUNK   4096               // elements per map block
#define NCHUNK  (N_SEQ / CHUNK)    // 4 chunks per row

#define INP2 36                    // padded row widths (odd multiple of 16B)
#define INP3 68
#define INP4 68

// -------------------------- device scratch ---------------------------------
__device__ __align__(8)  float2 g_tbl2[TBL_N];    // (f[i], f[i+1]) pairs
__device__ __align__(16) float4 g_coef[TBL_N];    // (G_i, a_i, b_i, 0)
__device__ float2 g_range;                        // (lo, inv_h)
__device__ float  g_h;                            // knot spacing

// -------------------------- math helpers -----------------------------------
__device__ __forceinline__ float splus(float x) {
    float e = __expf(-fabsf(x));
    return fmaxf(x, 0.0f) + __logf(1.0f + e);
}

__device__ __forceinline__ void block_minmax512(float& lo, float& hi,
                                                float* s_lo, float* s_hi) {
    unsigned m = 0xffffffffu;
#pragma unroll
    for (int off = 16; off > 0; off >>= 1) {
        lo = fminf(lo, __shfl_down_sync(m, lo, off));
        hi = fmaxf(hi, __shfl_down_sync(m, hi, off));
    }
    int warp = threadIdx.x >> 5, lane = threadIdx.x & 31;
    if (lane == 0) { s_lo[warp] = lo; s_hi[warp] = hi; }
    __syncthreads();
    if (warp == 0) {
        lo = (lane < 16) ? s_lo[lane] :  3.4e38f;
        hi = (lane < 16) ? s_hi[lane] : -3.4e38f;
#pragma unroll
        for (int off = 16; off > 0; off >>= 1) {
            lo = fminf(lo, __shfl_down_sync(m, lo, off));
            hi = fmaxf(hi, __shfl_down_sync(m, hi, off));
        }
        if (lane == 0) { s_lo[0] = lo; s_hi[0] = hi; }
    }
    __syncthreads();
    lo = s_lo[0]; hi = s_hi[0];
}

// t sorted per row: min = min(row heads), max = max(row tails)
__device__ __forceinline__ void edge_range(const float* __restrict__ t,
                                           int nrows,
                                           float& lo, float& hi,
                                           float* s_lo, float* s_hi) {
    int tid = threadIdx.x;
    float l = 3.4e38f, h = -3.4e38f;
    if (tid < nrows) {
        l = t[(size_t)tid * N_SEQ];
        h = t[(size_t)tid * N_SEQ + (N_SEQ - 1)];
    }
    for (int r = tid + 512; r < nrows; r += 512) {
        l = fminf(l, t[(size_t)r * N_SEQ]);
        h = fmaxf(h, t[(size_t)r * N_SEQ + (N_SEQ - 1)]);
    }
    block_minmax512(l, h, s_lo, s_hi);
    lo = l; hi = h;
}

// -------------------------- kernel 1: f at knots (warp-per-knot) ------------
// Weights kept row-major [unit][k] in smem (rows padded to odd-16B stride so
// cross-lane LDS.128 is conflict-free). Hidden vectors live in per-warp smem
// ping-pong buffers (broadcast LDS.128 reads).
__global__ __launch_bounds__(512) void table_kernel(
    const float* __restrict__ t, int nrows,
    const float* __restrict__ W1, const float* __restrict__ b1,
    const float* __restrict__ W2, const float* __restrict__ b2,
    const float* __restrict__ W3, const float* __restrict__ b3,
    const float* __restrict__ W4, const float* __restrict__ b4,
    const float* __restrict__ W5, const float* __restrict__ b5)
{
    __shared__ __align__(16) float sW2p[64 * INP2];
    __shared__ __align__(16) float sW3p[64 * INP3];
    __shared__ __align__(16) float sW4p[32 * INP4];
    __shared__ __align__(16) float sh[16][2][64];   // [warp][pingpong][unit]
    __shared__ float sW1[32], sB1[32], sB2[64], sB3[64], sB4[32], sW5[32];
    __shared__ float sB5;
    __shared__ float s_lo[16], s_hi[16];

    int tid = threadIdx.x;

    // coalesced staging (source index contiguous per thread step)
    for (int d = tid; d < 2048; d += 512) {        // W2 [64][32]
        int j = d >> 5, k = d & 31;
        sW2p[j * INP2 + k] = W2[d];
    }
    for (int d = tid; d < 4096; d += 512) {        // W3 [64][64]
        int j = d >> 6, k = d & 63;
        sW3p[j * INP3 + k] = W3[d];
    }
    for (int d = tid; d < 2048; d += 512) {        // W4 [32][64]
        int j = d >> 6, k = d & 63;
        sW4p[j * INP4 + k] = W4[d];
    }
    if (tid < 32) { sW1[tid] = W1[tid]; sB1[tid] = b1[tid];
                    sB4[tid] = b4[tid]; sW5[tid] = W5[tid]; }
    if (tid < 64) { sB2[tid] = b2[tid]; sB3[tid] = b3[tid]; }
    if (tid == 0) sB5 = b5[0];

    float lo, hi;
    edge_range(t, nrows, lo, hi, s_lo, s_hi);   // includes syncthreads
    float range = hi - lo;
    float h = (range > 1e-30f) ? range * (1.0f / TBL_N) : 1.0f;

    if (blockIdx.x == 0 && tid == 0) {
        float inv_h = (range > 1e-30f) ? (float)TBL_N / range : 0.0f;
        g_range = make_float2(lo, inv_h);
        g_h = h;
    }

    const unsigned m = 0xffffffffu;
    int wid  = tid >> 5;
    int lane = tid & 31;
    int kn = blockIdx.x * 16 + wid;          // knot index for this warp
    if (kn > TBL_N) return;
    float tv = lo + (float)kn * h;

    // ---- layer 1: 1 -> 32 ; lane j = unit j -> sh[wid][0][0..31]
    sh[wid][0][lane] = splus(fmaf(tv, sW1[lane], sB1[lane]));
    __syncwarp();

    // ---- layer 2: 32 -> 64 ; lane j handles units j, j+32
    {
        const float4* hv4 = reinterpret_cast<const float4*>(sh[wid][0]);
        const float4* w0r = reinterpret_cast<const float4*>(sW2p + lane * INP2);
        const float4* w1r = reinterpret_cast<const float4*>(sW2p + (lane + 32) * INP2);
        float a0 = sB2[lane], a1 = sB2[lane + 32];
#pragma unroll
        for (int k4 = 0; k4 < 8; k4++) {
            float4 hv = hv4[k4];
            float4 w0 = w0r[k4];
            float4 w1 = w1r[k4];
            a0 = fmaf(w0.x, hv.x, a0); a0 = fmaf(w0.y, hv.y, a0);
            a0 = fmaf(w0.z, hv.z, a0); a0 = fmaf(w0.w, hv.w, a0);
            a1 = fmaf(w1.x, hv.x, a1); a1 = fmaf(w1.y, hv.y, a1);
            a1 = fmaf(w1.z, hv.z, a1); a1 = fmaf(w1.w, hv.w, a1);
        }
        sh[wid][1][lane]      = splus(a0);
        sh[wid][1][lane + 32] = splus(a1);
    }
    __syncwarp();

    // ---- layer 3: 64 -> 64
    {
        const float4* hv4 = reinterpret_cast<const float4*>(sh[wid][1]);
        const float4* w0r = reinterpret_cast<const float4*>(sW3p + lane * INP3);
        const float4* w1r = reinterpret_cast<const float4*>(sW3p + (lane + 32) * INP3);
        float a0 = sB3[lane], a1 = sB3[lane + 32];
#pragma unroll
        for (int k4 = 0; k4 < 16; k4++) {
            float4 hv = hv4[k4];
            float4 w0 = w0r[k4];
            float4 w1 = w1r[k4];
            a0 = fmaf(w0.x, hv.x, a0); a0 = fmaf(w0.y, hv.y, a0);
            a0 = fmaf(w0.z, hv.z, a0); a0 = fmaf(w0.w, hv.w, a0);
            a1 = fmaf(w1.x, hv.x, a1); a1 = fmaf(w1.y, hv.y, a1);
            a1 = fmaf(w1.z, hv.z, a1); a1 = fmaf(w1.w, hv.w, a1);
        }
        sh[wid][0][lane]      = splus(a0);
        sh[wid][0][lane + 32] = splus(a1);
    }
    __syncwarp();

    // ---- layer 4: 64 -> 32 ; lane j = unit j
    float h4;
    {
        const float4* hv4 = reinterpret_cast<const float4*>(sh[wid][0]);
        const float4* w0r = reinterpret_cast<const float4*>(sW4p + lane * INP4);
        float a0 = sB4[lane];
#pragma unroll
        for (int k4 = 0; k4 < 16; k4++) {
            float4 hv = hv4[k4];
            float4 w0 = w0r[k4];
            a0 = fmaf(w0.x, hv.x, a0); a0 = fmaf(w0.y, hv.y, a0);
            a0 = fmaf(w0.z, hv.z, a0); a0 = fmaf(w0.w, hv.w, a0);
        }
        h4 = splus(a0);
    }

    // ---- layer 5: 32 -> 1 (warp reduce)
    float p = h4 * sW5[lane];
#pragma unroll
    for (int off = 16; off > 0; off >>= 1)
        p += __shfl_xor_sync(m, p, off);

    if (lane == 0) {
        float v = splus(p + sB5) + 1.0f;
        float* tbl = reinterpret_cast<float*>(g_tbl2);
        // slot kn: (f[kn], f[kn+1]); warp kn fills .x of kn and .y of kn-1.
        if (kn < TBL_N) tbl[2 * kn] = v;
        if (kn >= 1)    tbl[2 * (kn - 1) + 1] = v;
    }
}

// -------------------- kernel 2: antiderivative coefficients -----------------
// G(x) on interval i, frac = (x - x_i)/h in [0,1]:
//   G = G_i + a_i*frac + b_i*frac^2,  a_i = h*f_i,  b_i = 0.5*h*(f_{i+1}-f_i)
__global__ __launch_bounds__(512) void prefix_kernel()
{
    __shared__ float wsum[16];
    int tid = threadIdx.x;
    int lane = tid & 31, warp = tid >> 5;
    const unsigned m = 0xffffffffu;
    float h = g_h;

    int i0 = 2 * tid, i1 = 2 * tid + 1;
    float2 f0 = g_tbl2[i0];
    float2 f1 = g_tbl2[i1];
    float a0 = h * f0.x, b0 = 0.5f * h * (f0.y - f0.x);
    float a1 = h * f1.x, b1 = 0.5f * h * (f1.y - f1.x);
    float s0 = a0 + b0, s1 = a1 + b1;
    float tot = s0 + s1;

    float v = tot;
#pragma unroll
    for (int off = 1; off < 32; off <<= 1) {
        float n = __shfl_up_sync(m, v, off);
        if (lane >= off) v += n;
    }
    if (lane == 31) wsum[warp] = v;
    __syncthreads();
    if (warp == 0) {
        float w = (lane < 16) ? wsum[lane] : 0.0f;
#pragma unroll
        for (int off = 1; off < 16; off <<= 1) {
            float n = __shfl_up_sync(m, w, off);
            if (lane >= off) w += n;
        }
        if (lane < 16) wsum[lane] = w;
    }
    __syncthreads();

    float excl = ((warp > 0) ? wsum[warp - 1] : 0.0f) + (v - tot);
    g_coef[i0] = make_float4(excl,      a0, b0, 0.0f);
    g_coef[i1] = make_float4(excl + s0, a1, b1, 0.0f);
}

// -------------------------- kernel 3: pure map ------------------------------
#define S_THREADS 512
#define V4PT      (CHUNK / 4 / S_THREADS)  // 2 float4 per thread

__device__ __forceinline__ float evalG(float tv, float lo, float inv_h) {
    float u = (tv - lo) * inv_h;
    u = fminf(fmaxf(u, 0.0f), (float)TBL_N);
    int i = (int)u;
    if (i > TBL_N - 1) i = TBL_N - 1;
    float frac = u - (float)i;
    float4 c = __ldg(&g_coef[i]);
    return fmaf(frac, fmaf(frac, c.z, c.y), c.x);
}

__global__ __launch_bounds__(S_THREADS) void map_kernel(
    const float* __restrict__ t, float* __restrict__ out)
{
    int gid = blockIdx.x;
    int row = gid >> 2;                       // NCHUNK = 4
    size_t base = (size_t)row * N_SEQ + (size_t)(gid & (NCHUNK - 1)) * CHUNK;

    float2 rg = g_range;
    float lo = rg.x, inv_h = rg.y;

    // row anchor
    float G0 = evalG(__ldg(&t[(size_t)row * N_SEQ]), lo, inv_h);

    const float4* t4 = reinterpret_cast<const float4*>(t + base);
    float4* o4 = reinterpret_cast<float4*>(out + base);
    int tid = threadIdx.x;
#pragma unroll
    for (int w = 0; w < V4PT; w++) {
        int idx = tid + w * S_THREADS;
        float4 v = t4[idx];
        float4 o;
        o.x = evalG(v.x, lo, inv_h) - G0;
        o.y = evalG(v.y, lo, inv_h) - G0;
        o.z = evalG(v.z, lo, inv_h) - G0;
        o.w = evalG(v.w, lo, inv_h) - G0;
        o4[idx] = o;
    }
}

// ----------------------------------------------------------------------------
extern "C" void kernel_launch(void* const* d_in, const int* in_sizes, int n_in,
                              void* d_out, int out_size) {
    const float* t  = (const float*)d_in[0];
    const float* W1 = (const float*)d_in[1];
    const float* b1 = (const float*)d_in[2];
    const float* W2 = (const float*)d_in[3];
    const float* b2 = (const float*)d_in[4];
    const float* W3 = (const float*)d_in[5];
    const float* b3 = (const float*)d_in[6];
    const float* W4 = (const float*)d_in[7];
    const float* b4 = (const float*)d_in[8];
    const float* W5 = (const float*)d_in[9];
    const float* b5 = (const float*)d_in[10];
    float* out = (float*)d_out;

    int total = in_sizes[0];          // B * N
    int nrows = total / N_SEQ;        // B

    int tbl_blocks = (TBL_N + 1 + 15) / 16;    // 16 knots (warps) per block
    table_kernel<<<tbl_blocks, 512>>>(t, nrows, W1, b1, W2, b2, W3, b3,
                                      W4, b4, W5, b5);
    prefix_kernel<<<1, 512>>>();
    map_kernel<<<total / CHUNK, S_THREADS>>>(t, out);
}